// round 10
// baseline (speedup 1.0000x reference)
#include <cuda_runtime.h>

#define NNODE 50000
#define NEDGE 800000
#define HD 128
#define NLAYER 4
#define TE 64           // edges/nodes per block tile
#define TN 32           // nodes per pq-block
#define XP 68           // padded tile row (floats), 272B = 16B-aligned
#define XPN 36          // padded tile row for 32-wide tiles

__device__ float g_h[NNODE * HD];
__device__ float g_agg[NNODE * HD];
__device__ float g_P[NNODE * HD];
__device__ float g_Q[NNODE * HD];
__device__ float g_d2[NEDGE];

// ---- packed f32x2 helpers (sm_103a) ----
__device__ __forceinline__ void fma2(unsigned long long& a,
                                     unsigned long long x,
                                     unsigned long long w) {
    asm("fma.rn.f32x2 %0, %1, %2, %3;" : "=l"(a) : "l"(x), "l"(w), "l"(a));
}
__device__ __forceinline__ unsigned long long bcast2(float w) {
    unsigned long long r;
    asm("mov.b64 %0, {%1, %1};" : "=l"(r) : "r"(__float_as_uint(w)));
    return r;
}
__device__ __forceinline__ float2 unpack2(unsigned long long a) {
    unsigned lo, hi;
    asm("mov.b64 {%0, %1}, %2;" : "=r"(lo), "=r"(hi) : "l"(a));
    return make_float2(__uint_as_float(lo), __uint_as_float(hi));
}
__device__ __forceinline__ float silu(float x) {
    return x / (1.0f + __expf(-x));
}

__global__ void k_init(const int* __restrict__ z, const float* __restrict__ emb) {
    int i = blockIdx.x * 256 + threadIdx.x;
    if (i < NNODE * HD) {
        g_h[i] = emb[(z[i >> 7] << 7) | (i & 127)];
        g_agg[i] = 0.0f;
    }
}

__global__ void k_d2(const float* __restrict__ pos, const int* __restrict__ ei) {
    int e = blockIdx.x * 256 + threadIdx.x;
    if (e < NEDGE) {
        int r = ei[e], c = ei[NEDGE + e];
        float dx = pos[3 * r + 0] - pos[3 * c + 0];
        float dy = pos[3 * r + 1] - pos[3 * c + 1];
        float dz = pos[3 * r + 2] - pos[3 * c + 2];
        g_d2[e] = dx * dx + dy * dy + dz * dz;
    }
}

// P = h @ W1[0:128], Q = h @ W1[128:256]   (32 nodes per block, 256 threads)
__global__ __launch_bounds__(256) void k_pq(const float* __restrict__ W1) {
    __shared__ __align__(16) float xs[HD][XPN];

    const int tid = threadIdx.x;
    const int warp = tid >> 5, lane = tid & 31;
    const int n0 = blockIdx.x * TN;

    for (int r = warp; r < TN; r += 8) {
        int node = n0 + r;
        if (node >= NNODE) node = NNODE - 1;
        const float* src = g_h + (size_t)node * HD;
        #pragma unroll
        for (int s = 0; s < 4; s++)
            xs[lane + 32 * s][r] = src[lane + 32 * s];
    }
    __syncthreads();

    const int cp = tid & 63;          // col pair -> cols 2cp, 2cp+1
    const int q2 = (tid >> 6) & 1;    // node half: 16*q2
    const int g  = tid >> 7;          // 0 -> P, 1 -> Q
    const float* wp = W1 + (size_t)(g * 128) * HD + 2 * cp;

    unsigned long long a0[8], a1[8];
    #pragma unroll
    for (int q = 0; q < 8; q++) { a0[q] = 0ULL; a1[q] = 0ULL; }
    #pragma unroll 4
    for (int k = 0; k < HD; k++) {
        float2 w = __ldg((const float2*)(wp + (size_t)k * HD));
        unsigned long long w0 = bcast2(w.x), w1 = bcast2(w.y);
        const ulonglong2* xr = (const ulonglong2*)&xs[k][16 * q2];
        #pragma unroll
        for (int p = 0; p < 4; p++) {
            ulonglong2 pr = xr[p];
            fma2(a0[2*p+0], pr.x, w0); fma2(a0[2*p+1], pr.y, w0);
            fma2(a1[2*p+0], pr.x, w1); fma2(a1[2*p+1], pr.y, w1);
        }
    }
    float* dst = g ? g_Q : g_P;
    #pragma unroll
    for (int p = 0; p < 8; p++) {
        float2 v0 = unpack2(a0[p]);
        float2 v1 = unpack2(a1[p]);
        int na = n0 + 16 * q2 + 2 * p, nb = na + 1;
        if (na < NNODE) {
            dst[(size_t)na * HD + 2 * cp]     = v0.x;
            dst[(size_t)na * HD + 2 * cp + 1] = v1.x;
        }
        if (nb < NNODE) {
            dst[(size_t)nb * HD + 2 * cp]     = v0.y;
            dst[(size_t)nb * HD + 2 * cp + 1] = v1.y;
        }
    }
}

// Edge: u = silu(P[row] + Q[col] + d2*w1_last + b1); m = silu(u @ W2 + b2);
//       agg[row] += m.  64 edges x 128 cols, 256 threads = (quarter q4, colpair cp).
// __launch_bounds__(256, 5): cap regs at 51 -> 5 blocks/SM (40 warps).
__global__ __launch_bounds__(256, 5) void k_edge(
    const int* __restrict__ ei,
    const float* __restrict__ W1,            // row 256 = d2 weights
    const float* __restrict__ b1,
    const float* __restrict__ W2, const float* __restrict__ b2)
{
    __shared__ __align__(16) float xs[HD][XP];   // u transposed, ~35KB
    __shared__ int srow[TE], scol[TE];
    __shared__ float sd2[TE], s_b1[HD], s_wl[HD];

    const int tid = threadIdx.x;
    const int warp = tid >> 5, lane = tid & 31;
    const int e0 = blockIdx.x * TE;

    if (tid < TE) { srow[tid] = ei[e0 + tid]; sd2[tid] = g_d2[e0 + tid]; }
    else if (tid < 2 * TE) scol[tid - TE] = ei[NEDGE + e0 + (tid - TE)];
    if (tid < HD) {
        s_b1[tid] = __ldg(b1 + tid);
        s_wl[tid] = __ldg(W1 + 256 * HD + tid);
    }
    __syncthreads();

    // gather + add + silu -> xs[k][e]
    for (int r = warp; r < TE; r += 8) {
        const float* pp = g_P + (size_t)srow[r] * HD;
        const float* qq = g_Q + (size_t)scol[r] * HD;
        float d2e = sd2[r];
        #pragma unroll
        for (int s = 0; s < 4; s++) {
            int k = lane + 32 * s;
            float u = __ldg(pp + k) + __ldg(qq + k) + d2e * s_wl[k] + s_b1[k];
            xs[k][r] = silu(u);
        }
    }
    __syncthreads();

    const int cp = tid & 63;          // cols 2cp, 2cp+1
    const int q4 = tid >> 6;          // edges 16*q4 .. 16*q4+15
    const int eb = 16 * q4;
    unsigned long long a0[8], a1[8];
    #pragma unroll
    for (int q = 0; q < 8; q++) { a0[q] = 0ULL; a1[q] = 0ULL; }
    {
        const float* wp = W2 + 2 * cp;
        #pragma unroll 4
        for (int k = 0; k < HD; k++) {
            float2 w = __ldg((const float2*)(wp + (size_t)k * HD));
            unsigned long long w0 = bcast2(w.x), w1 = bcast2(w.y);
            const ulonglong2* xr = (const ulonglong2*)&xs[k][eb];
            #pragma unroll
            for (int p = 0; p < 4; p++) {
                ulonglong2 pr = xr[p];
                fma2(a0[2*p+0], pr.x, w0); fma2(a0[2*p+1], pr.y, w0);
                fma2(a1[2*p+0], pr.x, w1); fma2(a1[2*p+1], pr.y, w1);
            }
        }
    }
    {
        float2 bb = __ldg((const float2*)(b2 + 2 * cp));
        #pragma unroll
        for (int p = 0; p < 8; p++) {
            float2 v0 = unpack2(a0[p]);
            float2 v1 = unpack2(a1[p]);
            int ea = eb + 2 * p;
            float* ra = g_agg + (size_t)srow[ea] * HD;
            float* rb = g_agg + (size_t)srow[ea + 1] * HD;
            atomicAdd(ra + 2 * cp,     silu(v0.x + bb.x));
            atomicAdd(ra + 2 * cp + 1, silu(v1.x + bb.y));
            atomicAdd(rb + 2 * cp,     silu(v0.y + bb.x));
            atomicAdd(rb + 2 * cp + 1, silu(v1.y + bb.y));
        }
    }
}

// Node MLP + residual + LayerNorm. 64 nodes per block, 256 threads.
__global__ __launch_bounds__(256) void k_node(
    const float* __restrict__ W1, const float* __restrict__ b1,
    const float* __restrict__ W2, const float* __restrict__ b2,
    const float* __restrict__ lng, const float* __restrict__ lnb,
    float* __restrict__ out, int use_out)
{
    __shared__ __align__(16) float xs[2 * HD][XP];  // ~70KB
    __shared__ float ys[TE][132];                   // ~34KB

    const int tid = threadIdx.x;
    const int warp = tid >> 5, lane = tid & 31;
    const int n0 = blockIdx.x * TE;

    for (int r = warp; r < 2 * TE; r += 8) {
        int e = r & (TE - 1);
        int node = n0 + e;
        if (node >= NNODE) node = 0;
        const float* src = (r < TE) ? (g_h + (size_t)node * HD)
                                    : (g_agg + (size_t)node * HD);
        int kb = (r < TE) ? 0 : HD;
        #pragma unroll
        for (int s = 0; s < 4; s++)
            xs[kb + lane + 32 * s][e] = src[lane + 32 * s];
    }
    __syncthreads();

    const int cp = tid & 63;
    const int q4 = tid >> 6;
    const int eb = 16 * q4;

    // zero agg rows for next layer (block exclusively owns them)
    {
        int j = tid & 127;
        int ho = (tid >> 7) << 5;
        #pragma unroll
        for (int q = 0; q < 32; q++) {
            int node = n0 + ho + q;
            if (node < NNODE) g_agg[(size_t)node * HD + j] = 0.0f;
        }
    }

    unsigned long long a0[8], a1[8];

    // GEMM1: [64 x 256] @ [256 x 128], silu
    #pragma unroll
    for (int q = 0; q < 8; q++) { a0[q] = 0ULL; a1[q] = 0ULL; }
    {
        const float* wp = W1 + 2 * cp;
        #pragma unroll 4
        for (int k = 0; k < 2 * HD; k++) {
            float2 w = __ldg((const float2*)(wp + (size_t)k * HD));
            unsigned long long w0 = bcast2(w.x), w1 = bcast2(w.y);
            const ulonglong2* xr = (const ulonglong2*)&xs[k][eb];
            #pragma unroll
            for (int p = 0; p < 4; p++) {
                ulonglong2 pr = xr[p];
                fma2(a0[2*p+0], pr.x, w0); fma2(a0[2*p+1], pr.y, w0);
                fma2(a1[2*p+0], pr.x, w1); fma2(a1[2*p+1], pr.y, w1);
            }
        }
    }
    __syncthreads();   // agg half of xs dead; activated tile -> rows 128..255
    {
        float2 bb = __ldg((const float2*)(b1 + 2 * cp));
        #pragma unroll
        for (int p = 0; p < 8; p++) {
            float2 v0 = unpack2(a0[p]);
            float2 v1 = unpack2(a1[p]);
            int ea = eb + 2 * p;
            xs[HD + 2 * cp][ea]         = silu(v0.x + bb.x);
            xs[HD + 2 * cp][ea + 1]     = silu(v0.y + bb.x);
            xs[HD + 2 * cp + 1][ea]     = silu(v1.x + bb.y);
            xs[HD + 2 * cp + 1][ea + 1] = silu(v1.y + bb.y);
        }
    }
    __syncthreads();

    // GEMM2: [64 x 128] @ [128 x 128]; + residual from xs rows 0..127
    #pragma unroll
    for (int q = 0; q < 8; q++) { a0[q] = 0ULL; a1[q] = 0ULL; }
    {
        const float* wp = W2 + 2 * cp;
        #pragma unroll 4
        for (int k = 0; k < HD; k++) {
            float2 w = __ldg((const float2*)(wp + (size_t)k * HD));
            unsigned long long w0 = bcast2(w.x), w1 = bcast2(w.y);
            const ulonglong2* xr = (const ulonglong2*)&xs[HD + k][eb];
            #pragma unroll
            for (int p = 0; p < 4; p++) {
                ulonglong2 pr = xr[p];
                fma2(a0[2*p+0], pr.x, w0); fma2(a0[2*p+1], pr.y, w0);
                fma2(a1[2*p+0], pr.x, w1); fma2(a1[2*p+1], pr.y, w1);
            }
        }
    }
    {
        float2 bb = __ldg((const float2*)(b2 + 2 * cp));
        #pragma unroll
        for (int p = 0; p < 8; p++) {
            float2 v0 = unpack2(a0[p]);
            float2 v1 = unpack2(a1[p]);
            int ea = eb + 2 * p;
            ys[ea][2 * cp]         = v0.x + bb.x + xs[2 * cp][ea];
            ys[ea + 1][2 * cp]     = v0.y + bb.x + xs[2 * cp][ea + 1];
            ys[ea][2 * cp + 1]     = v1.x + bb.y + xs[2 * cp + 1][ea];
            ys[ea + 1][2 * cp + 1] = v1.y + bb.y + xs[2 * cp + 1][ea + 1];
        }
    }
    __syncthreads();

    // LayerNorm: each warp handles 8 nodes
    float* hout = use_out ? out : g_h;
    #pragma unroll
    for (int t = 0; t < 8; t++) {
        int e = warp * 8 + t;
        int node = n0 + e;
        float v0 = ys[e][lane +  0];
        float v1 = ys[e][lane + 32];
        float v2 = ys[e][lane + 64];
        float v3 = ys[e][lane + 96];
        float s  = v0 + v1 + v2 + v3;
        float ss = fmaf(v0, v0, fmaf(v1, v1, fmaf(v2, v2, v3 * v3)));
        #pragma unroll
        for (int o = 16; o; o >>= 1) {
            s  += __shfl_xor_sync(0xffffffffu, s, o);
            ss += __shfl_xor_sync(0xffffffffu, ss, o);
        }
        float mu  = s * (1.0f / 128.0f);
        float inv = rsqrtf(ss * (1.0f / 128.0f) - mu * mu + 1e-5f);
        if (node < NNODE) {
            float* dst = hout + (size_t)node * HD;
            dst[lane +  0] = fmaf(__ldg(lng + lane +  0), (v0 - mu) * inv, __ldg(lnb + lane +  0));
            dst[lane + 32] = fmaf(__ldg(lng + lane + 32), (v1 - mu) * inv, __ldg(lnb + lane + 32));
            dst[lane + 64] = fmaf(__ldg(lng + lane + 64), (v2 - mu) * inv, __ldg(lnb + lane + 64));
            dst[lane + 96] = fmaf(__ldg(lng + lane + 96), (v3 - mu) * inv, __ldg(lnb + lane + 96));
        }
    }
}

extern "C" void kernel_launch(void* const* d_in, const int* in_sizes, int n_in,
                              void* d_out, int out_size) {
    const int*   z   = (const int*)d_in[0];
    const float* pos = (const float*)d_in[1];
    const int*   ei  = (const int*)d_in[2];
    const float* emb = (const float*)d_in[3];
    const float* ew1 = (const float*)d_in[4];
    const float* eb1 = (const float*)d_in[5];
    const float* ew2 = (const float*)d_in[6];
    const float* eb2 = (const float*)d_in[7];
    const float* nw1 = (const float*)d_in[8];
    const float* nb1 = (const float*)d_in[9];
    const float* nw2 = (const float*)d_in[10];
    const float* nb2 = (const float*)d_in[11];
    const float* lng = (const float*)d_in[12];
    const float* lnb = (const float*)d_in[13];
    float* out = (float*)d_out;

    k_init<<<(NNODE * HD + 255) / 256, 256>>>(z, emb);
    k_d2<<<(NEDGE + 255) / 256, 256>>>(pos, ei);

    const int pqgrid = (NNODE + TN - 1) / TN;   // 1563
    const int egrid  = NEDGE / TE;              // 12500
    const int ngrid  = (NNODE + TE - 1) / TE;   // 782

    for (int l = 0; l < NLAYER; l++) {
        const float* W1l = ew1 + (size_t)l * 257 * HD;
        k_pq<<<pqgrid, 256>>>(W1l);
        k_edge<<<egrid, 256>>>(ei, W1l, eb1 + l * HD,
                               ew2 + (size_t)l * HD * HD, eb2 + l * HD);
        k_node<<<ngrid, 256>>>(nw1 + (size_t)l * 2 * HD * HD, nb1 + l * HD,
                               nw2 + (size_t)l * HD * HD,     nb2 + l * HD,
                               lng + l * HD, lnb + l * HD,
                               out, (l == NLAYER - 1) ? 1 : 0);
    }
}

// round 11
// speedup vs baseline: 1.3373x; 1.3373x over previous
#include <cuda_runtime.h>
#include <cuda_bf16.h>
#include <cstdint>

#define NNODE 50000
#define NEDGE 800000
#define HD 128
#define NLAYER 4
#define TE 64           // edges/nodes per block tile
#define TN 32           // nodes per pq-block
#define XP 68           // padded tile row (floats), 272B = 16B-aligned
#define XPN 36          // padded tile row for 32-wide tiles

__device__ float g_h[NNODE * HD];
__device__ float g_agg[NNODE * HD];
__device__ float g_P[NNODE * HD];
__device__ float g_Q[NNODE * HD];
__device__ float g_d2[NEDGE];
// split-bf16 W2 image, col-major: [layer][n*128 + kp*2 + {0:hi,1:lo}]
// word = packed bf16x2 of (W2[2kp][n], W2[2kp+1][n])
__device__ uint32_t g_w2te[NLAYER][128 * 128];

// ---- packed f32x2 helpers (sm_103a) ----
__device__ __forceinline__ void fma2(unsigned long long& a,
                                     unsigned long long x,
                                     unsigned long long w) {
    asm("fma.rn.f32x2 %0, %1, %2, %3;" : "=l"(a) : "l"(x), "l"(w), "l"(a));
}
__device__ __forceinline__ unsigned long long bcast2(float w) {
    unsigned long long r;
    asm("mov.b64 %0, {%1, %1};" : "=l"(r) : "r"(__float_as_uint(w)));
    return r;
}
__device__ __forceinline__ float2 unpack2(unsigned long long a) {
    unsigned lo, hi;
    asm("mov.b64 {%0, %1}, %2;" : "=r"(lo), "=r"(hi) : "l"(a));
    return make_float2(__uint_as_float(lo), __uint_as_float(hi));
}
__device__ __forceinline__ float silu(float x) {
    return x / (1.0f + __expf(-x));
}
__device__ __forceinline__ uint32_t packbf(float lo_e, float hi_e) {
    // lo_e -> low 16 bits
    return ((uint32_t)__bfloat16_as_ushort(__float2bfloat16_rn(hi_e)) << 16)
         |  (uint32_t)__bfloat16_as_ushort(__float2bfloat16_rn(lo_e));
}

// m16n8k16 bf16 mma, fp32 accumulate (sm_80+ PTX)
#define MMA_BF16(c, a0, a1, a2, a3, b0, b1) \
    asm volatile("mma.sync.aligned.m16n8k16.row.col.f32.bf16.bf16.f32 " \
        "{%0,%1,%2,%3}, {%4,%5,%6,%7}, {%8,%9}, {%0,%1,%2,%3};" \
        : "+f"((c)[0]), "+f"((c)[1]), "+f"((c)[2]), "+f"((c)[3]) \
        : "r"(a0), "r"(a1), "r"(a2), "r"(a3), "r"(b0), "r"(b1))

__global__ void k_init(const int* __restrict__ z, const float* __restrict__ emb) {
    int i = blockIdx.x * 256 + threadIdx.x;
    if (i < NNODE * HD) {
        g_h[i] = emb[(z[i >> 7] << 7) | (i & 127)];
        g_agg[i] = 0.0f;
    }
}

__global__ void k_d2(const float* __restrict__ pos, const int* __restrict__ ei) {
    int e = blockIdx.x * 256 + threadIdx.x;
    if (e < NEDGE) {
        int r = ei[e], c = ei[NEDGE + e];
        float dx = pos[3 * r + 0] - pos[3 * c + 0];
        float dy = pos[3 * r + 1] - pos[3 * c + 1];
        float dz = pos[3 * r + 2] - pos[3 * c + 2];
        g_d2[e] = dx * dx + dy * dy + dz * dz;
    }
}

// Build split-bf16 col-major W2 image (hi/lo interleaved per word-pair)
__global__ void k_prepw2(const float* __restrict__ ew2) {
    int idx = blockIdx.x * 256 + threadIdx.x;     // NLAYER * 128 * 64
    if (idx >= NLAYER * 128 * 64) return;
    int l = idx >> 13, r = idx & 8191, n = r >> 6, kp = r & 63;
    const float* W = ew2 + (size_t)l * HD * HD;
    float w0 = W[(size_t)(2 * kp) * HD + n];
    float w1 = W[(size_t)(2 * kp + 1) * HD + n];
    __nv_bfloat16 h0 = __float2bfloat16_rn(w0), h1 = __float2bfloat16_rn(w1);
    float l0 = w0 - __bfloat162float(h0), l1 = w1 - __bfloat162float(h1);
    g_w2te[l][n * 128 + kp * 2 + 0] =
        ((uint32_t)__bfloat16_as_ushort(h1) << 16) | __bfloat16_as_ushort(h0);
    g_w2te[l][n * 128 + kp * 2 + 1] = packbf(l0, l1);
}

// P = h @ W1[0:128], Q = h @ W1[128:256]   (32 nodes per block, 256 threads)
__global__ __launch_bounds__(256) void k_pq(const float* __restrict__ W1) {
    __shared__ __align__(16) float xs[HD][XPN];

    const int tid = threadIdx.x;
    const int warp = tid >> 5, lane = tid & 31;
    const int n0 = blockIdx.x * TN;

    for (int r = warp; r < TN; r += 8) {
        int node = n0 + r;
        if (node >= NNODE) node = NNODE - 1;
        const float* src = g_h + (size_t)node * HD;
        #pragma unroll
        for (int s = 0; s < 4; s++)
            xs[lane + 32 * s][r] = src[lane + 32 * s];
    }
    __syncthreads();

    const int cp = tid & 63;
    const int q2 = (tid >> 6) & 1;
    const int g  = tid >> 7;
    const float* wp = W1 + (size_t)(g * 128) * HD + 2 * cp;

    unsigned long long a0[8], a1[8];
    #pragma unroll
    for (int q = 0; q < 8; q++) { a0[q] = 0ULL; a1[q] = 0ULL; }
    #pragma unroll 4
    for (int k = 0; k < HD; k++) {
        float2 w = __ldg((const float2*)(wp + (size_t)k * HD));
        unsigned long long w0 = bcast2(w.x), w1 = bcast2(w.y);
        const ulonglong2* xr = (const ulonglong2*)&xs[k][16 * q2];
        #pragma unroll
        for (int p = 0; p < 4; p++) {
            ulonglong2 pr = xr[p];
            fma2(a0[2*p+0], pr.x, w0); fma2(a0[2*p+1], pr.y, w0);
            fma2(a1[2*p+0], pr.x, w1); fma2(a1[2*p+1], pr.y, w1);
        }
    }
    float* dst = g ? g_Q : g_P;
    #pragma unroll
    for (int p = 0; p < 8; p++) {
        float2 v0 = unpack2(a0[p]);
        float2 v1 = unpack2(a1[p]);
        int na = n0 + 16 * q2 + 2 * p, nb = na + 1;
        if (na < NNODE) {
            dst[(size_t)na * HD + 2 * cp]     = v0.x;
            dst[(size_t)na * HD + 2 * cp + 1] = v1.x;
        }
        if (nb < NNODE) {
            dst[(size_t)nb * HD + 2 * cp]     = v0.y;
            dst[(size_t)nb * HD + 2 * cp + 1] = v1.y;
        }
    }
}

// Edge: u = silu(P[row] + Q[col] + d2*w1_last + b1); m = silu(u @ W2 + b2);
//       agg[row] += m.
// 64 edges x 128 cols per block, 256 threads (8 warps).
// GEMM2 on tensor cores: split-bf16 m16n8k16 mma.sync, 3 products (hi*hi+lo*hi+hi*lo).
// Warp tile: 16 edges (mi=warp&3) x 64 cols (ni=warp>>2) = 8 n8-subtiles.
__global__ __launch_bounds__(256) void k_edge(
    const int* __restrict__ ei,
    const float* __restrict__ W1,            // row 256 = d2 weights
    const float* __restrict__ b1,
    const float* __restrict__ b2, int layer)
{
    __shared__ uint32_t xhi[TE][68];   // packed bf16x2 hi plane, padded stride
    __shared__ uint32_t xlo[TE][68];   // lo plane
    __shared__ int srow[TE], scols[TE];
    __shared__ float sd2[TE], s_b1[HD], s_wl[HD];

    const int tid = threadIdx.x;
    const int warp = tid >> 5, lane = tid & 31;
    const int e0 = blockIdx.x * TE;

    if (tid < TE) { srow[tid] = ei[e0 + tid]; sd2[tid] = g_d2[e0 + tid]; }
    else if (tid < 2 * TE) scols[tid - TE] = ei[NEDGE + e0 + (tid - TE)];
    if (tid < HD) {
        s_b1[tid] = __ldg(b1 + tid);
        s_wl[tid] = __ldg(W1 + 256 * HD + tid);
    }
    __syncthreads();

    // gather + silu + split-bf16 -> xhi/xlo[e][kpair]
    for (int e = warp; e < TE; e += 8) {
        const float* pp = g_P + (size_t)srow[e] * HD;
        const float* qq = g_Q + (size_t)scols[e] * HD;
        float d2e = sd2[e];
        #pragma unroll
        for (int s = 0; s < 2; s++) {
            int kp = lane + 32 * s;
            float2 pv = __ldg((const float2*)(pp + 2 * kp));
            float2 qv = __ldg((const float2*)(qq + 2 * kp));
            float u0 = silu(pv.x + qv.x + d2e * s_wl[2 * kp]     + s_b1[2 * kp]);
            float u1 = silu(pv.y + qv.y + d2e * s_wl[2 * kp + 1] + s_b1[2 * kp + 1]);
            __nv_bfloat16 h0 = __float2bfloat16_rn(u0);
            __nv_bfloat16 h1 = __float2bfloat16_rn(u1);
            xhi[e][kp] = ((uint32_t)__bfloat16_as_ushort(h1) << 16)
                       |  (uint32_t)__bfloat16_as_ushort(h0);
            xlo[e][kp] = packbf(u0 - __bfloat162float(h0),
                                u1 - __bfloat162float(h1));
        }
    }
    __syncthreads();

    const int g = lane >> 2, t = lane & 3;
    const int m0 = 16 * (warp & 3);
    const int n0 = 64 * (warp >> 2);

    float c[8][4];
    #pragma unroll
    for (int s = 0; s < 8; s++)
        #pragma unroll
        for (int q = 0; q < 4; q++) c[s][q] = 0.0f;

    const uint32_t* bw = &g_w2te[layer][0];

    #pragma unroll
    for (int ks = 0; ks < 8; ks++) {
        // A fragments (standard m16k16 row-major layout)
        uint32_t a0h = xhi[m0 + g][8 * ks + t];
        uint32_t a1h = xhi[m0 + 8 + g][8 * ks + t];
        uint32_t a2h = xhi[m0 + g][8 * ks + 4 + t];
        uint32_t a3h = xhi[m0 + 8 + g][8 * ks + 4 + t];
        uint32_t a0l = xlo[m0 + g][8 * ks + t];
        uint32_t a1l = xlo[m0 + 8 + g][8 * ks + t];
        uint32_t a2l = xlo[m0 + g][8 * ks + 4 + t];
        uint32_t a3l = xlo[m0 + 8 + g][8 * ks + 4 + t];
        #pragma unroll
        for (int s = 0; s < 8; s++) {
            const uint32_t* bp = bw + (size_t)(n0 + 8 * s + g) * 128;
            uint2 B0 = __ldg((const uint2*)(bp + (8 * ks + t) * 2));      // (b0h, b0l)
            uint2 B1 = __ldg((const uint2*)(bp + (8 * ks + 4 + t) * 2));  // (b1h, b1l)
            MMA_BF16(c[s], a0h, a1h, a2h, a3h, B0.x, B1.x);   // hi*hi
            MMA_BF16(c[s], a0l, a1l, a2l, a3l, B0.x, B1.x);   // lo*hi
            MMA_BF16(c[s], a0h, a1h, a2h, a3h, B0.y, B1.y);   // hi*lo
        }
    }

    // epilogue: silu(+b2), atomic scatter.
    // C layout: c0,c1 = row g, cols 2t,2t+1; c2,c3 = row g+8.
    {
        float* ra = g_agg + (size_t)srow[m0 + g] * HD;
        float* rb = g_agg + (size_t)srow[m0 + 8 + g] * HD;
        #pragma unroll
        for (int s = 0; s < 8; s++) {
            int col = n0 + 8 * s + 2 * t;
            float bb0 = __ldg(b2 + col), bb1 = __ldg(b2 + col + 1);
            atomicAdd(ra + col,     silu(c[s][0] + bb0));
            atomicAdd(ra + col + 1, silu(c[s][1] + bb1));
            atomicAdd(rb + col,     silu(c[s][2] + bb0));
            atomicAdd(rb + col + 1, silu(c[s][3] + bb1));
        }
    }
}

// Node MLP + residual + LayerNorm. 64 nodes per block, 256 threads. (Round-6 version)
__global__ __launch_bounds__(256) void k_node(
    const float* __restrict__ W1, const float* __restrict__ b1,
    const float* __restrict__ W2, const float* __restrict__ b2,
    const float* __restrict__ lng, const float* __restrict__ lnb,
    float* __restrict__ out, int use_out)
{
    __shared__ __align__(16) float xs[2 * HD][XP];
    __shared__ float ys[TE][132];

    const int tid = threadIdx.x;
    const int warp = tid >> 5, lane = tid & 31;
    const int n0 = blockIdx.x * TE;

    for (int r = warp; r < 2 * TE; r += 8) {
        int e = r & (TE - 1);
        int node = n0 + e;
        if (node >= NNODE) node = 0;
        const float* src = (r < TE) ? (g_h + (size_t)node * HD)
                                    : (g_agg + (size_t)node * HD);
        int kb = (r < TE) ? 0 : HD;
        #pragma unroll
        for (int s = 0; s < 4; s++)
            xs[kb + lane + 32 * s][e] = src[lane + 32 * s];
    }
    __syncthreads();

    const int cp = tid & 63;
    const int q4 = tid >> 6;
    const int eb = 16 * q4;

    {
        int j = tid & 127;
        int ho = (tid >> 7) << 5;
        #pragma unroll
        for (int q = 0; q < 32; q++) {
            int node = n0 + ho + q;
            if (node < NNODE) g_agg[(size_t)node * HD + j] = 0.0f;
        }
    }

    unsigned long long a0[8], a1[8];

    #pragma unroll
    for (int q = 0; q < 8; q++) { a0[q] = 0ULL; a1[q] = 0ULL; }
    {
        const float* wp = W1 + 2 * cp;
        #pragma unroll 4
        for (int k = 0; k < 2 * HD; k++) {
            float2 w = __ldg((const float2*)(wp + (size_t)k * HD));
            unsigned long long w0 = bcast2(w.x), w1 = bcast2(w.y);
            const ulonglong2* xr = (const ulonglong2*)&xs[k][eb];
            #pragma unroll
            for (int p = 0; p < 4; p++) {
                ulonglong2 pr = xr[p];
                fma2(a0[2*p+0], pr.x, w0); fma2(a0[2*p+1], pr.y, w0);
                fma2(a1[2*p+0], pr.x, w1); fma2(a1[2*p+1], pr.y, w1);
            }
        }
    }
    __syncthreads();
    {
        float2 bb = __ldg((const float2*)(b1 + 2 * cp));
        #pragma unroll
        for (int p = 0; p < 8; p++) {
            float2 v0 = unpack2(a0[p]);
            float2 v1 = unpack2(a1[p]);
            int ea = eb + 2 * p;
            xs[HD + 2 * cp][ea]         = silu(v0.x + bb.x);
            xs[HD + 2 * cp][ea + 1]     = silu(v0.y + bb.x);
            xs[HD + 2 * cp + 1][ea]     = silu(v1.x + bb.y);
            xs[HD + 2 * cp + 1][ea + 1] = silu(v1.y + bb.y);
        }
    }
    __syncthreads();

    #pragma unroll
    for (int q = 0; q < 8; q++) { a0[q] = 0ULL; a1[q] = 0ULL; }
    {
        const float* wp = W2 + 2 * cp;
        #pragma unroll 4
        for (int k = 0; k < HD; k++) {
            float2 w = __ldg((const float2*)(wp + (size_t)k * HD));
            unsigned long long w0 = bcast2(w.x), w1 = bcast2(w.y);
            const ulonglong2* xr = (const ulonglong2*)&xs[HD + k][eb];
            #pragma unroll
            for (int p = 0; p < 4; p++) {
                ulonglong2 pr = xr[p];
                fma2(a0[2*p+0], pr.x, w0); fma2(a0[2*p+1], pr.y, w0);
                fma2(a1[2*p+0], pr.x, w1); fma2(a1[2*p+1], pr.y, w1);
            }
        }
    }
    {
        float2 bb = __ldg((const float2*)(b2 + 2 * cp));
        #pragma unroll
        for (int p = 0; p < 8; p++) {
            float2 v0 = unpack2(a0[p]);
            float2 v1 = unpack2(a1[p]);
            int ea = eb + 2 * p;
            ys[ea][2 * cp]         = v0.x + bb.x + xs[2 * cp][ea];
            ys[ea + 1][2 * cp]     = v0.y + bb.x + xs[2 * cp][ea + 1];
            ys[ea][2 * cp + 1]     = v1.x + bb.y + xs[2 * cp + 1][ea];
            ys[ea + 1][2 * cp + 1] = v1.y + bb.y + xs[2 * cp + 1][ea + 1];
        }
    }
    __syncthreads();

    float* hout = use_out ? out : g_h;
    #pragma unroll
    for (int t = 0; t < 8; t++) {
        int e = warp * 8 + t;
        int node = n0 + e;
        float v0 = ys[e][lane +  0];
        float v1 = ys[e][lane + 32];
        float v2 = ys[e][lane + 64];
        float v3 = ys[e][lane + 96];
        float s  = v0 + v1 + v2 + v3;
        float ss = fmaf(v0, v0, fmaf(v1, v1, fmaf(v2, v2, v3 * v3)));
        #pragma unroll
        for (int o = 16; o; o >>= 1) {
            s  += __shfl_xor_sync(0xffffffffu, s, o);
            ss += __shfl_xor_sync(0xffffffffu, ss, o);
        }
        float mu  = s * (1.0f / 128.0f);
        float inv = rsqrtf(ss * (1.0f / 128.0f) - mu * mu + 1e-5f);
        if (node < NNODE) {
            float* dst = hout + (size_t)node * HD;
            dst[lane +  0] = fmaf(__ldg(lng + lane +  0), (v0 - mu) * inv, __ldg(lnb + lane +  0));
            dst[lane + 32] = fmaf(__ldg(lng + lane + 32), (v1 - mu) * inv, __ldg(lnb + lane + 32));
            dst[lane + 64] = fmaf(__ldg(lng + lane + 64), (v2 - mu) * inv, __ldg(lnb + lane + 64));
            dst[lane + 96] = fmaf(__ldg(lng + lane + 96), (v3 - mu) * inv, __ldg(lnb + lane + 96));
        }
    }
}

extern "C" void kernel_launch(void* const* d_in, const int* in_sizes, int n_in,
                              void* d_out, int out_size) {
    const int*   z   = (const int*)d_in[0];
    const float* pos = (const float*)d_in[1];
    const int*   ei  = (const int*)d_in[2];
    const float* emb = (const float*)d_in[3];
    const float* ew1 = (const float*)d_in[4];
    const float* eb1 = (const float*)d_in[5];
    const float* ew2 = (const float*)d_in[6];
    const float* eb2 = (const float*)d_in[7];
    const float* nw1 = (const float*)d_in[8];
    const float* nb1 = (const float*)d_in[9];
    const float* nw2 = (const float*)d_in[10];
    const float* nb2 = (const float*)d_in[11];
    const float* lng = (const float*)d_in[12];
    const float* lnb = (const float*)d_in[13];
    float* out = (float*)d_out;

    k_init<<<(NNODE * HD + 255) / 256, 256>>>(z, emb);
    k_d2<<<(NEDGE + 255) / 256, 256>>>(pos, ei);
    k_prepw2<<<(NLAYER * 128 * 64 + 255) / 256, 256>>>(ew2);

    const int pqgrid = (NNODE + TN - 1) / TN;   // 1563
    const int egrid  = NEDGE / TE;              // 12500
    const int ngrid  = (NNODE + TE - 1) / TE;   // 782

    for (int l = 0; l < NLAYER; l++) {
        const float* W1l = ew1 + (size_t)l * 257 * HD;
        k_pq<<<pqgrid, 256>>>(W1l);
        k_edge<<<egrid, 256>>>(ei, W1l, eb1 + l * HD, eb2 + l * HD, l);
        k_node<<<ngrid, 256>>>(nw1 + (size_t)l * 2 * HD * HD, nb1 + l * HD,
                               nw2 + (size_t)l * HD * HD,     nb2 + l * HD,
                               lng + l * HD, lnb + l * HD,
                               out, (l == NLAYER - 1) ? 1 : 0);
    }
}

// round 12
// speedup vs baseline: 1.7225x; 1.2881x over previous
#include <cuda_runtime.h>
#include <cuda_bf16.h>
#include <cstdint>

#define NNODE 50000
#define NEDGE 800000
#define HD 128
#define NLAYER 4
#define TE 64           // edges/nodes per block tile
#define TN 32           // nodes per pq-block
#define XP 68           // padded tile row (floats), 272B = 16B-aligned
#define XPN 36          // padded tile row for 32-wide tiles

__device__ float g_h[NNODE * HD];
__device__ float g_agg[NNODE * HD];
__device__ float g_P[NNODE * HD];
__device__ float g_Q[NNODE * HD];
__device__ float g_d2[NEDGE];
// W2 image, fragment-major: [layer][(ks*16 + s)*32 + lane] =
//   uint4(B0hi, B0lo, B1hi, B1lo) for col n=8s+g, kpairs kp0=8ks+t, kp1=kp0+4
//   (g=lane>>2, t=lane&3). One coalesced LDG.128 per warp per (ks,s).
__device__ uint4 g_w2te[NLAYER][4096];

// ---- packed f32x2 helpers (sm_103a) ----
__device__ __forceinline__ void fma2(unsigned long long& a,
                                     unsigned long long x,
                                     unsigned long long w) {
    asm("fma.rn.f32x2 %0, %1, %2, %3;" : "=l"(a) : "l"(x), "l"(w), "l"(a));
}
__device__ __forceinline__ unsigned long long bcast2(float w) {
    unsigned long long r;
    asm("mov.b64 %0, {%1, %1};" : "=l"(r) : "r"(__float_as_uint(w)));
    return r;
}
__device__ __forceinline__ float2 unpack2(unsigned long long a) {
    unsigned lo, hi;
    asm("mov.b64 {%0, %1}, %2;" : "=r"(lo), "=r"(hi) : "l"(a));
    return make_float2(__uint_as_float(lo), __uint_as_float(hi));
}
__device__ __forceinline__ float silu(float x) {
    return x / (1.0f + __expf(-x));
}
__device__ __forceinline__ uint32_t packbf(float lo_e, float hi_e) {
    // lo_e -> low 16 bits
    return ((uint32_t)__bfloat16_as_ushort(__float2bfloat16_rn(hi_e)) << 16)
         |  (uint32_t)__bfloat16_as_ushort(__float2bfloat16_rn(lo_e));
}

// m16n8k16 bf16 mma, fp32 accumulate (sm_80+ PTX)
#define MMA_BF16(c, a0, a1, a2, a3, b0, b1) \
    asm volatile("mma.sync.aligned.m16n8k16.row.col.f32.bf16.bf16.f32 " \
        "{%0,%1,%2,%3}, {%4,%5,%6,%7}, {%8,%9}, {%0,%1,%2,%3};" \
        : "+f"((c)[0]), "+f"((c)[1]), "+f"((c)[2]), "+f"((c)[3]) \
        : "r"(a0), "r"(a1), "r"(a2), "r"(a3), "r"(b0), "r"(b1))

__global__ void k_init(const int* __restrict__ z, const float* __restrict__ emb) {
    int i = blockIdx.x * 256 + threadIdx.x;
    if (i < NNODE * HD) {
        g_h[i] = emb[(z[i >> 7] << 7) | (i & 127)];
        g_agg[i] = 0.0f;
    }
}

__global__ void k_d2(const float* __restrict__ pos, const int* __restrict__ ei) {
    int e = blockIdx.x * 256 + threadIdx.x;
    if (e < NEDGE) {
        int r = ei[e], c = ei[NEDGE + e];
        float dx = pos[3 * r + 0] - pos[3 * c + 0];
        float dy = pos[3 * r + 1] - pos[3 * c + 1];
        float dz = pos[3 * r + 2] - pos[3 * c + 2];
        g_d2[e] = dx * dx + dy * dy + dz * dz;
    }
}

// Build fragment-major split-bf16 W2 image.
__global__ void k_prepw2(const float* __restrict__ ew2) {
    int idx = blockIdx.x * 256 + threadIdx.x;     // NLAYER * 4096
    if (idx >= NLAYER * 4096) return;
    int l = idx >> 12, r = idx & 4095;
    int ks = r >> 9, s = (r >> 5) & 15, lane = r & 31;
    int g = lane >> 2, t = lane & 3;
    int n = 8 * s + g;
    int kp0 = 8 * ks + t, kp1 = kp0 + 4;
    const float* W = ew2 + (size_t)l * HD * HD;

    float w00 = W[(size_t)(2 * kp0) * HD + n];
    float w01 = W[(size_t)(2 * kp0 + 1) * HD + n];
    float w10 = W[(size_t)(2 * kp1) * HD + n];
    float w11 = W[(size_t)(2 * kp1 + 1) * HD + n];
    __nv_bfloat16 h00 = __float2bfloat16_rn(w00), h01 = __float2bfloat16_rn(w01);
    __nv_bfloat16 h10 = __float2bfloat16_rn(w10), h11 = __float2bfloat16_rn(w11);

    uint4 v;
    v.x = ((uint32_t)__bfloat16_as_ushort(h01) << 16) | __bfloat16_as_ushort(h00);
    v.y = packbf(w00 - __bfloat162float(h00), w01 - __bfloat162float(h01));
    v.z = ((uint32_t)__bfloat16_as_ushort(h11) << 16) | __bfloat16_as_ushort(h10);
    v.w = packbf(w10 - __bfloat162float(h10), w11 - __bfloat162float(h11));
    g_w2te[l][r] = v;
}

// P = h @ W1[0:128], Q = h @ W1[128:256]   (32 nodes per block, 256 threads)
__global__ __launch_bounds__(256) void k_pq(const float* __restrict__ W1) {
    __shared__ __align__(16) float xs[HD][XPN];

    const int tid = threadIdx.x;
    const int warp = tid >> 5, lane = tid & 31;
    const int n0 = blockIdx.x * TN;

    for (int r = warp; r < TN; r += 8) {
        int node = n0 + r;
        if (node >= NNODE) node = NNODE - 1;
        const float* src = g_h + (size_t)node * HD;
        #pragma unroll
        for (int s = 0; s < 4; s++)
            xs[lane + 32 * s][r] = src[lane + 32 * s];
    }
    __syncthreads();

    const int cp = tid & 63;
    const int q2 = (tid >> 6) & 1;
    const int g  = tid >> 7;
    const float* wp = W1 + (size_t)(g * 128) * HD + 2 * cp;

    unsigned long long a0[8], a1[8];
    #pragma unroll
    for (int q = 0; q < 8; q++) { a0[q] = 0ULL; a1[q] = 0ULL; }
    #pragma unroll 4
    for (int k = 0; k < HD; k++) {
        float2 w = __ldg((const float2*)(wp + (size_t)k * HD));
        unsigned long long w0 = bcast2(w.x), w1 = bcast2(w.y);
        const ulonglong2* xr = (const ulonglong2*)&xs[k][16 * q2];
        #pragma unroll
        for (int p = 0; p < 4; p++) {
            ulonglong2 pr = xr[p];
            fma2(a0[2*p+0], pr.x, w0); fma2(a0[2*p+1], pr.y, w0);
            fma2(a1[2*p+0], pr.x, w1); fma2(a1[2*p+1], pr.y, w1);
        }
    }
    float* dst = g ? g_Q : g_P;
    #pragma unroll
    for (int p = 0; p < 8; p++) {
        float2 v0 = unpack2(a0[p]);
        float2 v1 = unpack2(a1[p]);
        int na = n0 + 16 * q2 + 2 * p, nb = na + 1;
        if (na < NNODE) {
            dst[(size_t)na * HD + 2 * cp]     = v0.x;
            dst[(size_t)na * HD + 2 * cp + 1] = v1.x;
        }
        if (nb < NNODE) {
            dst[(size_t)nb * HD + 2 * cp]     = v0.y;
            dst[(size_t)nb * HD + 2 * cp + 1] = v1.y;
        }
    }
}

// Edge: u = silu(P[row] + Q[col] + d2*w1_last + b1); m = silu(u @ W2 + b2);
//       agg[row] += m.
// 64 edges x 128 cols per block, 256 threads (8 warps).
// GEMM2 on tensor cores: split-bf16 m16n8k16 mma.sync, 3 products.
// Warp tile: 16 edges (warp&3) x 64 cols (warp>>2). B via coalesced LDG.128.
__global__ __launch_bounds__(256) void k_edge(
    const int* __restrict__ ei,
    const float* __restrict__ W1,            // row 256 = d2 weights
    const float* __restrict__ b1,
    const float* __restrict__ b2, int layer)
{
    __shared__ uint32_t xhi[TE][68];   // packed bf16x2 hi plane, padded stride
    __shared__ uint32_t xlo[TE][68];   // lo plane
    __shared__ int srow[TE], scols[TE];
    __shared__ float sd2[TE], s_b1[HD], s_wl[HD];

    const int tid = threadIdx.x;
    const int warp = tid >> 5, lane = tid & 31;
    const int e0 = blockIdx.x * TE;

    if (tid < TE) { srow[tid] = ei[e0 + tid]; sd2[tid] = g_d2[e0 + tid]; }
    else if (tid < 2 * TE) scols[tid - TE] = ei[NEDGE + e0 + (tid - TE)];
    if (tid < HD) {
        s_b1[tid] = __ldg(b1 + tid);
        s_wl[tid] = __ldg(W1 + 256 * HD + tid);
    }
    __syncthreads();

    // gather + silu + split-bf16 -> xhi/xlo[e][kpair]
    for (int e = warp; e < TE; e += 8) {
        const float* pp = g_P + (size_t)srow[e] * HD;
        const float* qq = g_Q + (size_t)scols[e] * HD;
        float d2e = sd2[e];
        #pragma unroll
        for (int s = 0; s < 2; s++) {
            int kp = lane + 32 * s;
            float2 pv = __ldg((const float2*)(pp + 2 * kp));
            float2 qv = __ldg((const float2*)(qq + 2 * kp));
            float u0 = silu(pv.x + qv.x + d2e * s_wl[2 * kp]     + s_b1[2 * kp]);
            float u1 = silu(pv.y + qv.y + d2e * s_wl[2 * kp + 1] + s_b1[2 * kp + 1]);
            __nv_bfloat16 h0 = __float2bfloat16_rn(u0);
            __nv_bfloat16 h1 = __float2bfloat16_rn(u1);
            xhi[e][kp] = ((uint32_t)__bfloat16_as_ushort(h1) << 16)
                       |  (uint32_t)__bfloat16_as_ushort(h0);
            xlo[e][kp] = packbf(u0 - __bfloat162float(h0),
                                u1 - __bfloat162float(h1));
        }
    }
    __syncthreads();

    const int g = lane >> 2, t = lane & 3;
    const int m0 = 16 * (warp & 3);
    const int sbase = (warp >> 2) * 8;   // s_global base: 0 or 8
    const int n0 = 8 * sbase;

    float c[8][4];
    #pragma unroll
    for (int s = 0; s < 8; s++)
        #pragma unroll
        for (int q = 0; q < 4; q++) c[s][q] = 0.0f;

    const uint4* bw = &g_w2te[layer][0];

    #pragma unroll
    for (int ks = 0; ks < 8; ks++) {
        // A fragments (standard m16k16 row-major layout)
        uint32_t a0h = xhi[m0 + g][8 * ks + t];
        uint32_t a1h = xhi[m0 + 8 + g][8 * ks + t];
        uint32_t a2h = xhi[m0 + g][8 * ks + 4 + t];
        uint32_t a3h = xhi[m0 + 8 + g][8 * ks + 4 + t];
        uint32_t a0l = xlo[m0 + g][8 * ks + t];
        uint32_t a1l = xlo[m0 + 8 + g][8 * ks + t];
        uint32_t a2l = xlo[m0 + g][8 * ks + 4 + t];
        uint32_t a3l = xlo[m0 + 8 + g][8 * ks + 4 + t];
        #pragma unroll
        for (int s = 0; s < 8; s++) {
            uint4 B = __ldg(bw + ((ks * 16 + sbase + s) * 32 + lane));
            MMA_BF16(c[s], a0h, a1h, a2h, a3h, B.x, B.z);   // hi*hi
            MMA_BF16(c[s], a0l, a1l, a2l, a3l, B.x, B.z);   // lo*hi
            MMA_BF16(c[s], a0h, a1h, a2h, a3h, B.y, B.w);   // hi*lo
        }
    }

    // epilogue: silu(+b2), atomic scatter.
    // C layout: c0,c1 = row g, cols 2t,2t+1; c2,c3 = row g+8.
    {
        float* ra = g_agg + (size_t)srow[m0 + g] * HD;
        float* rb = g_agg + (size_t)srow[m0 + 8 + g] * HD;
        #pragma unroll
        for (int s = 0; s < 8; s++) {
            int col = n0 + 8 * s + 2 * t;
            float bb0 = __ldg(b2 + col), bb1 = __ldg(b2 + col + 1);
            atomicAdd(ra + col,     silu(c[s][0] + bb0));
            atomicAdd(ra + col + 1, silu(c[s][1] + bb1));
            atomicAdd(rb + col,     silu(c[s][2] + bb0));
            atomicAdd(rb + col + 1, silu(c[s][3] + bb1));
        }
    }
}

// Node MLP + residual + LayerNorm. 64 nodes per block, 256 threads. (Round-6 version)
__global__ __launch_bounds__(256) void k_node(
    const float* __restrict__ W1, const float* __restrict__ b1,
    const float* __restrict__ W2, const float* __restrict__ b2,
    const float* __restrict__ lng, const float* __restrict__ lnb,
    float* __restrict__ out, int use_out)
{
    __shared__ __align__(16) float xs[2 * HD][XP];
    __shared__ float ys[TE][132];

    const int tid = threadIdx.x;
    const int warp = tid >> 5, lane = tid & 31;
    const int n0 = blockIdx.x * TE;

    for (int r = warp; r < 2 * TE; r += 8) {
        int e = r & (TE - 1);
        int node = n0 + e;
        if (node >= NNODE) node = 0;
        const float* src = (r < TE) ? (g_h + (size_t)node * HD)
                                    : (g_agg + (size_t)node * HD);
        int kb = (r < TE) ? 0 : HD;
        #pragma unroll
        for (int s = 0; s < 4; s++)
            xs[kb + lane + 32 * s][e] = src[lane + 32 * s];
    }
    __syncthreads();

    const int cp = tid & 63;
    const int q4 = tid >> 6;
    const int eb = 16 * q4;

    {
        int j = tid & 127;
        int ho = (tid >> 7) << 5;
        #pragma unroll
        for (int q = 0; q < 32; q++) {
            int node = n0 + ho + q;
            if (node < NNODE) g_agg[(size_t)node * HD + j] = 0.0f;
        }
    }

    unsigned long long a0[8], a1[8];

    #pragma unroll
    for (int q = 0; q < 8; q++) { a0[q] = 0ULL; a1[q] = 0ULL; }
    {
        const float* wp = W1 + 2 * cp;
        #pragma unroll 4
        for (int k = 0; k < 2 * HD; k++) {
            float2 w = __ldg((const float2*)(wp + (size_t)k * HD));
            unsigned long long w0 = bcast2(w.x), w1 = bcast2(w.y);
            const ulonglong2* xr = (const ulonglong2*)&xs[k][eb];
            #pragma unroll
            for (int p = 0; p < 4; p++) {
                ulonglong2 pr = xr[p];
                fma2(a0[2*p+0], pr.x, w0); fma2(a0[2*p+1], pr.y, w0);
                fma2(a1[2*p+0], pr.x, w1); fma2(a1[2*p+1], pr.y, w1);
            }
        }
    }
    __syncthreads();
    {
        float2 bb = __ldg((const float2*)(b1 + 2 * cp));
        #pragma unroll
        for (int p = 0; p < 8; p++) {
            float2 v0 = unpack2(a0[p]);
            float2 v1 = unpack2(a1[p]);
            int ea = eb + 2 * p;
            xs[HD + 2 * cp][ea]         = silu(v0.x + bb.x);
            xs[HD + 2 * cp][ea + 1]     = silu(v0.y + bb.x);
            xs[HD + 2 * cp + 1][ea]     = silu(v1.x + bb.y);
            xs[HD + 2 * cp + 1][ea + 1] = silu(v1.y + bb.y);
        }
    }
    __syncthreads();

    #pragma unroll
    for (int q = 0; q < 8; q++) { a0[q] = 0ULL; a1[q] = 0ULL; }
    {
        const float* wp = W2 + 2 * cp;
        #pragma unroll 4
        for (int k = 0; k < HD; k++) {
            float2 w = __ldg((const float2*)(wp + (size_t)k * HD));
            unsigned long long w0 = bcast2(w.x), w1 = bcast2(w.y);
            const ulonglong2* xr = (const ulonglong2*)&xs[HD + k][eb];
            #pragma unroll
            for (int p = 0; p < 4; p++) {
                ulonglong2 pr = xr[p];
                fma2(a0[2*p+0], pr.x, w0); fma2(a0[2*p+1], pr.y, w0);
                fma2(a1[2*p+0], pr.x, w1); fma2(a1[2*p+1], pr.y, w1);
            }
        }
    }
    {
        float2 bb = __ldg((const float2*)(b2 + 2 * cp));
        #pragma unroll
        for (int p = 0; p < 8; p++) {
            float2 v0 = unpack2(a0[p]);
            float2 v1 = unpack2(a1[p]);
            int ea = eb + 2 * p;
            ys[ea][2 * cp]         = v0.x + bb.x + xs[2 * cp][ea];
            ys[ea + 1][2 * cp]     = v0.y + bb.x + xs[2 * cp][ea + 1];
            ys[ea][2 * cp + 1]     = v1.x + bb.y + xs[2 * cp + 1][ea];
            ys[ea + 1][2 * cp + 1] = v1.y + bb.y + xs[2 * cp + 1][ea + 1];
        }
    }
    __syncthreads();

    float* hout = use_out ? out : g_h;
    #pragma unroll
    for (int t = 0; t < 8; t++) {
        int e = warp * 8 + t;
        int node = n0 + e;
        float v0 = ys[e][lane +  0];
        float v1 = ys[e][lane + 32];
        float v2 = ys[e][lane + 64];
        float v3 = ys[e][lane + 96];
        float s  = v0 + v1 + v2 + v3;
        float ss = fmaf(v0, v0, fmaf(v1, v1, fmaf(v2, v2, v3 * v3)));
        #pragma unroll
        for (int o = 16; o; o >>= 1) {
            s  += __shfl_xor_sync(0xffffffffu, s, o);
            ss += __shfl_xor_sync(0xffffffffu, ss, o);
        }
        float mu  = s * (1.0f / 128.0f);
        float inv = rsqrtf(ss * (1.0f / 128.0f) - mu * mu + 1e-5f);
        if (node < NNODE) {
            float* dst = hout + (size_t)node * HD;
            dst[lane +  0] = fmaf(__ldg(lng + lane +  0), (v0 - mu) * inv, __ldg(lnb + lane +  0));
            dst[lane + 32] = fmaf(__ldg(lng + lane + 32), (v1 - mu) * inv, __ldg(lnb + lane + 32));
            dst[lane + 64] = fmaf(__ldg(lng + lane + 64), (v2 - mu) * inv, __ldg(lnb + lane + 64));
            dst[lane + 96] = fmaf(__ldg(lng + lane + 96), (v3 - mu) * inv, __ldg(lnb + lane + 96));
        }
    }
}

extern "C" void kernel_launch(void* const* d_in, const int* in_sizes, int n_in,
                              void* d_out, int out_size) {
    const int*   z   = (const int*)d_in[0];
    const float* pos = (const float*)d_in[1];
    const int*   ei  = (const int*)d_in[2];
    const float* emb = (const float*)d_in[3];
    const float* ew1 = (const float*)d_in[4];
    const float* eb1 = (const float*)d_in[5];
    const float* ew2 = (const float*)d_in[6];
    const float* eb2 = (const float*)d_in[7];
    const float* nw1 = (const float*)d_in[8];
    const float* nb1 = (const float*)d_in[9];
    const float* nw2 = (const float*)d_in[10];
    const float* nb2 = (const float*)d_in[11];
    const float* lng = (const float*)d_in[12];
    const float* lnb = (const float*)d_in[13];
    float* out = (float*)d_out;

    k_init<<<(NNODE * HD + 255) / 256, 256>>>(z, emb);
    k_d2<<<(NEDGE + 255) / 256, 256>>>(pos, ei);
    k_prepw2<<<(NLAYER * 4096 + 255) / 256, 256>>>(ew2);

    const int pqgrid = (NNODE + TN - 1) / TN;   // 1563
    const int egrid  = NEDGE / TE;              // 12500
    const int ngrid  = (NNODE + TE - 1) / TE;   // 782

    for (int l = 0; l < NLAYER; l++) {
        const float* W1l = ew1 + (size_t)l * 257 * HD;
        k_pq<<<pqgrid, 256>>>(W1l);
        k_edge<<<egrid, 256>>>(ei, W1l, eb1 + l * HD, eb2 + l * HD, l);
        k_node<<<ngrid, 256>>>(nw1 + (size_t)l * 2 * HD * HD, nb1 + l * HD,
                               nw2 + (size_t)l * HD * HD,     nb2 + l * HD,
                               lng + l * HD, lnb + l * HD,
                               out, (l == NLAYER - 1) ? 1 : 0);
    }
}

// round 13
// speedup vs baseline: 1.7410x; 1.0108x over previous
#include <cuda_runtime.h>
#include <cuda_bf16.h>
#include <cstdint>

#define NNODE 50000
#define NEDGE 800000
#define HD 128
#define NLAYER 4
#define TE 64           // edges/nodes per block tile
#define TN 32           // nodes per pq-block
#define XPN 36          // padded tile row for 32-wide tiles

__device__ float g_h[NNODE * HD];
__device__ float g_agg[NNODE * HD];
__device__ float g_P[NNODE * HD];
__device__ float g_Q[NNODE * HD];
__device__ float g_d2[NEDGE];
// fragment-major split-bf16 weight images:
// entry r=(ks*16+s)*32+lane -> uint4(B0hi,B0lo,B1hi,B1lo), col n=8s+(lane>>2),
// kpairs kp0=8ks+(lane&3), kp1=kp0+4. One coalesced LDG.128 per warp per (ks,s).
__device__ uint4 g_w2te[NLAYER][4096];    // edge W2,  K=128
__device__ uint4 g_nw1te[NLAYER][8192];   // node W1,  K=256
__device__ uint4 g_nw2te[NLAYER][4096];   // node W2,  K=128

// ---- packed f32x2 helpers (sm_103a) ----
__device__ __forceinline__ void fma2(unsigned long long& a,
                                     unsigned long long x,
                                     unsigned long long w) {
    asm("fma.rn.f32x2 %0, %1, %2, %3;" : "=l"(a) : "l"(x), "l"(w), "l"(a));
}
__device__ __forceinline__ unsigned long long bcast2(float w) {
    unsigned long long r;
    asm("mov.b64 %0, {%1, %1};" : "=l"(r) : "r"(__float_as_uint(w)));
    return r;
}
__device__ __forceinline__ float2 unpack2(unsigned long long a) {
    unsigned lo, hi;
    asm("mov.b64 {%0, %1}, %2;" : "=r"(lo), "=r"(hi) : "l"(a));
    return make_float2(__uint_as_float(lo), __uint_as_float(hi));
}
__device__ __forceinline__ float silu(float x) {
    return x / (1.0f + __expf(-x));
}
__device__ __forceinline__ uint32_t packbf(float lo_e, float hi_e) {
    // lo_e -> low 16 bits
    return ((uint32_t)__bfloat16_as_ushort(__float2bfloat16_rn(hi_e)) << 16)
         |  (uint32_t)__bfloat16_as_ushort(__float2bfloat16_rn(lo_e));
}
// split a float2 into hi/lo packed bf16x2 words
__device__ __forceinline__ void splitbf(float2 v, uint32_t& hiw, uint32_t& low) {
    __nv_bfloat16 h0 = __float2bfloat16_rn(v.x);
    __nv_bfloat16 h1 = __float2bfloat16_rn(v.y);
    hiw = ((uint32_t)__bfloat16_as_ushort(h1) << 16)
        |  (uint32_t)__bfloat16_as_ushort(h0);
    low = packbf(v.x - __bfloat162float(h0), v.y - __bfloat162float(h1));
}

// m16n8k16 bf16 mma, fp32 accumulate (sm_80+ PTX)
#define MMA_BF16(c, a0, a1, a2, a3, b0, b1) \
    asm volatile("mma.sync.aligned.m16n8k16.row.col.f32.bf16.bf16.f32 " \
        "{%0,%1,%2,%3}, {%4,%5,%6,%7}, {%8,%9}, {%0,%1,%2,%3};" \
        : "+f"((c)[0]), "+f"((c)[1]), "+f"((c)[2]), "+f"((c)[3]) \
        : "r"(a0), "r"(a1), "r"(a2), "r"(a3), "r"(b0), "r"(b1))

__global__ void k_init(const int* __restrict__ z, const float* __restrict__ emb) {
    int i = blockIdx.x * 256 + threadIdx.x;
    if (i < NNODE * HD) {
        g_h[i] = emb[(z[i >> 7] << 7) | (i & 127)];
        g_agg[i] = 0.0f;
    }
}

__global__ void k_d2(const float* __restrict__ pos, const int* __restrict__ ei) {
    int e = blockIdx.x * 256 + threadIdx.x;
    if (e < NEDGE) {
        int r = ei[e], c = ei[NEDGE + e];
        float dx = pos[3 * r + 0] - pos[3 * c + 0];
        float dy = pos[3 * r + 1] - pos[3 * c + 1];
        float dz = pos[3 * r + 2] - pos[3 * c + 2];
        g_d2[e] = dx * dx + dy * dy + dz * dz;
    }
}

// Generic fragment-major split-bf16 weight image builder.
// which: 0 -> g_w2te(K=128), 1 -> g_nw1te(K=256), 2 -> g_nw2te(K=128)
__global__ void k_prepw(const float* __restrict__ src, int ksteps,
                        int layer_stride, int which) {
    int per = ksteps * 512;
    int idx = blockIdx.x * 256 + threadIdx.x;
    if (idx >= NLAYER * per) return;
    int l = idx / per, r = idx % per;
    int ks = r >> 9, s = (r >> 5) & 15, lane = r & 31;
    int g = lane >> 2, t = lane & 3;
    int n = 8 * s + g;
    int kp0 = 8 * ks + t, kp1 = kp0 + 4;
    const float* W = src + (size_t)l * layer_stride;

    float w00 = W[(size_t)(2 * kp0) * HD + n];
    float w01 = W[(size_t)(2 * kp0 + 1) * HD + n];
    float w10 = W[(size_t)(2 * kp1) * HD + n];
    float w11 = W[(size_t)(2 * kp1 + 1) * HD + n];
    uint4 v;
    splitbf(make_float2(w00, w01), v.x, v.y);
    splitbf(make_float2(w10, w11), v.z, v.w);
    if (which == 0)      g_w2te[l][r] = v;
    else if (which == 1) g_nw1te[l][r] = v;
    else                 g_nw2te[l][r] = v;
}

// P = h @ W1[0:128], Q = h @ W1[128:256]   (32 nodes per block, 256 threads)
__global__ __launch_bounds__(256) void k_pq(const float* __restrict__ W1) {
    __shared__ __align__(16) float xs[HD][XPN];

    const int tid = threadIdx.x;
    const int warp = tid >> 5, lane = tid & 31;
    const int n0 = blockIdx.x * TN;

    for (int r = warp; r < TN; r += 8) {
        int node = n0 + r;
        if (node >= NNODE) node = NNODE - 1;
        const float* src = g_h + (size_t)node * HD;
        #pragma unroll
        for (int s = 0; s < 4; s++)
            xs[lane + 32 * s][r] = src[lane + 32 * s];
    }
    __syncthreads();

    const int cp = tid & 63;
    const int q2 = (tid >> 6) & 1;
    const int g  = tid >> 7;
    const float* wp = W1 + (size_t)(g * 128) * HD + 2 * cp;

    unsigned long long a0[8], a1[8];
    #pragma unroll
    for (int q = 0; q < 8; q++) { a0[q] = 0ULL; a1[q] = 0ULL; }
    #pragma unroll 4
    for (int k = 0; k < HD; k++) {
        float2 w = __ldg((const float2*)(wp + (size_t)k * HD));
        unsigned long long w0 = bcast2(w.x), w1 = bcast2(w.y);
        const ulonglong2* xr = (const ulonglong2*)&xs[k][16 * q2];
        #pragma unroll
        for (int p = 0; p < 4; p++) {
            ulonglong2 pr = xr[p];
            fma2(a0[2*p+0], pr.x, w0); fma2(a0[2*p+1], pr.y, w0);
            fma2(a1[2*p+0], pr.x, w1); fma2(a1[2*p+1], pr.y, w1);
        }
    }
    float* dst = g ? g_Q : g_P;
    #pragma unroll
    for (int p = 0; p < 8; p++) {
        float2 v0 = unpack2(a0[p]);
        float2 v1 = unpack2(a1[p]);
        int na = n0 + 16 * q2 + 2 * p, nb = na + 1;
        if (na < NNODE) {
            dst[(size_t)na * HD + 2 * cp]     = v0.x;
            dst[(size_t)na * HD + 2 * cp + 1] = v1.x;
        }
        if (nb < NNODE) {
            dst[(size_t)nb * HD + 2 * cp]     = v0.y;
            dst[(size_t)nb * HD + 2 * cp + 1] = v1.y;
        }
    }
}

// Edge kernel (Round-12, proven): tensor-core GEMM2 with coalesced B image.
__global__ __launch_bounds__(256) void k_edge(
    const int* __restrict__ ei,
    const float* __restrict__ W1,            // row 256 = d2 weights
    const float* __restrict__ b1,
    const float* __restrict__ b2, int layer)
{
    __shared__ uint32_t xhi[TE][68];
    __shared__ uint32_t xlo[TE][68];
    __shared__ int srow[TE], scols[TE];
    __shared__ float sd2[TE], s_b1[HD], s_wl[HD];

    const int tid = threadIdx.x;
    const int warp = tid >> 5, lane = tid & 31;
    const int e0 = blockIdx.x * TE;

    if (tid < TE) { srow[tid] = ei[e0 + tid]; sd2[tid] = g_d2[e0 + tid]; }
    else if (tid < 2 * TE) scols[tid - TE] = ei[NEDGE + e0 + (tid - TE)];
    if (tid < HD) {
        s_b1[tid] = __ldg(b1 + tid);
        s_wl[tid] = __ldg(W1 + 256 * HD + tid);
    }
    __syncthreads();

    for (int e = warp; e < TE; e += 8) {
        const float* pp = g_P + (size_t)srow[e] * HD;
        const float* qq = g_Q + (size_t)scols[e] * HD;
        float d2e = sd2[e];
        #pragma unroll
        for (int s = 0; s < 2; s++) {
            int kp = lane + 32 * s;
            float2 pv = __ldg((const float2*)(pp + 2 * kp));
            float2 qv = __ldg((const float2*)(qq + 2 * kp));
            float u0 = silu(pv.x + qv.x + d2e * s_wl[2 * kp]     + s_b1[2 * kp]);
            float u1 = silu(pv.y + qv.y + d2e * s_wl[2 * kp + 1] + s_b1[2 * kp + 1]);
            splitbf(make_float2(u0, u1), xhi[e][kp], xlo[e][kp]);
        }
    }
    __syncthreads();

    const int g = lane >> 2, t = lane & 3;
    const int m0 = 16 * (warp & 3);
    const int sbase = (warp >> 2) * 8;
    const int n0 = 8 * sbase;

    float c[8][4];
    #pragma unroll
    for (int s = 0; s < 8; s++)
        #pragma unroll
        for (int q = 0; q < 4; q++) c[s][q] = 0.0f;

    const uint4* bw = &g_w2te[layer][0];

    #pragma unroll
    for (int ks = 0; ks < 8; ks++) {
        uint32_t a0h = xhi[m0 + g][8 * ks + t];
        uint32_t a1h = xhi[m0 + 8 + g][8 * ks + t];
        uint32_t a2h = xhi[m0 + g][8 * ks + 4 + t];
        uint32_t a3h = xhi[m0 + 8 + g][8 * ks + 4 + t];
        uint32_t a0l = xlo[m0 + g][8 * ks + t];
        uint32_t a1l = xlo[m0 + 8 + g][8 * ks + t];
        uint32_t a2l = xlo[m0 + g][8 * ks + 4 + t];
        uint32_t a3l = xlo[m0 + 8 + g][8 * ks + 4 + t];
        #pragma unroll
        for (int s = 0; s < 8; s++) {
            uint4 B = __ldg(bw + ((ks * 16 + sbase + s) * 32 + lane));
            MMA_BF16(c[s], a0h, a1h, a2h, a3h, B.x, B.z);
            MMA_BF16(c[s], a0l, a1l, a2l, a3l, B.x, B.z);
            MMA_BF16(c[s], a0h, a1h, a2h, a3h, B.y, B.w);
        }
    }

    {
        float* ra = g_agg + (size_t)srow[m0 + g] * HD;
        float* rb = g_agg + (size_t)srow[m0 + 8 + g] * HD;
        #pragma unroll
        for (int s = 0; s < 8; s++) {
            int col = n0 + 8 * s + 2 * t;
            float bb0 = __ldg(b2 + col), bb1 = __ldg(b2 + col + 1);
            atomicAdd(ra + col,     silu(c[s][0] + bb0));
            atomicAdd(ra + col + 1, silu(c[s][1] + bb1));
            atomicAdd(rb + col,     silu(c[s][2] + bb0));
            atomicAdd(rb + col + 1, silu(c[s][3] + bb1));
        }
    }
}

// Node MLP + residual + LayerNorm on tensor cores.
// 64 nodes x 128 cols, 256 threads (8 warps). Same warp tiling as k_edge.
// smem phases: xhi/xlo[64][132] (K=256 input planes) -> thi/tlo[64][68]
// (activated planes, overlay) -> ys[64][132] (LN transpose, overlay).
__global__ __launch_bounds__(256) void k_node(
    const float* __restrict__ b1, const float* __restrict__ b2,
    const float* __restrict__ lng, const float* __restrict__ lnb,
    float* __restrict__ out, int use_out, int layer)
{
    __shared__ __align__(16) unsigned char sbuf0[64 * 132 * 4];
    __shared__ __align__(16) unsigned char sbuf1[64 * 132 * 4];
    __shared__ float s_b1[HD], s_b2[HD], s_g[HD], s_bb[HD];

    uint32_t (*xhi)[132] = (uint32_t(*)[132])sbuf0;
    uint32_t (*xlo)[132] = (uint32_t(*)[132])sbuf1;
    uint32_t (*thi)[68]  = (uint32_t(*)[68])sbuf0;
    uint32_t (*tlo)[68]  = (uint32_t(*)[68])sbuf1;
    float (*ys)[132]     = (float(*)[132])sbuf0;

    const int tid = threadIdx.x;
    const int warp = tid >> 5, lane = tid & 31;
    const int nb0 = blockIdx.x * TE;

    if (tid < HD) {
        s_b1[tid] = __ldg(b1 + tid);
        s_b2[tid] = __ldg(b2 + tid);
        s_g[tid]  = __ldg(lng + tid);
        s_bb[tid] = __ldg(lnb + tid);
    }

    // gather [h | agg] -> split-bf16 planes; zero agg for next layer
    for (int r = warp; r < TE; r += 8) {
        int node = nb0 + r;
        int valid = node < NNODE;
        if (!valid) node = 0;
        const float* hp = g_h + (size_t)node * HD;
        float* ap = g_agg + (size_t)node * HD;
        #pragma unroll
        for (int s = 0; s < 2; s++) {
            int kp = lane + 32 * s;
            float2 hv = __ldg((const float2*)(hp + 2 * kp));
            splitbf(hv, xhi[r][kp], xlo[r][kp]);
            float2 av = *(const float2*)(ap + 2 * kp);
            splitbf(av, xhi[r][64 + kp], xlo[r][64 + kp]);
            if (valid) *(float2*)(ap + 2 * kp) = make_float2(0.f, 0.f);
        }
    }
    __syncthreads();

    const int g = lane >> 2, t = lane & 3;
    const int m0 = 16 * (warp & 3);
    const int sbase = (warp >> 2) * 8;
    const int n0 = 8 * sbase;
    const int r0 = m0 + g, r1 = m0 + 8 + g;

    float c[8][4];
    #pragma unroll
    for (int s = 0; s < 8; s++)
        #pragma unroll
        for (int q = 0; q < 4; q++) c[s][q] = 0.0f;

    // GEMM1: [64 x 256] @ [256 x 128]
    {
        const uint4* bw = &g_nw1te[layer][0];
        #pragma unroll
        for (int ks = 0; ks < 16; ks++) {
            uint32_t a0h = xhi[r0][8 * ks + t];
            uint32_t a1h = xhi[r1][8 * ks + t];
            uint32_t a2h = xhi[r0][8 * ks + 4 + t];
            uint32_t a3h = xhi[r1][8 * ks + 4 + t];
            uint32_t a0l = xlo[r0][8 * ks + t];
            uint32_t a1l = xlo[r1][8 * ks + t];
            uint32_t a2l = xlo[r0][8 * ks + 4 + t];
            uint32_t a3l = xlo[r1][8 * ks + 4 + t];
            #pragma unroll
            for (int s = 0; s < 8; s++) {
                uint4 B = __ldg(bw + ((ks * 16 + sbase + s) * 32 + lane));
                MMA_BF16(c[s], a0h, a1h, a2h, a3h, B.x, B.z);
                MMA_BF16(c[s], a0l, a1l, a2l, a3l, B.x, B.z);
                MMA_BF16(c[s], a0h, a1h, a2h, a3h, B.y, B.w);
            }
        }
    }
    __syncthreads();   // x planes dead; write activated t planes (overlay)

    #pragma unroll
    for (int s = 0; s < 8; s++) {
        int col = n0 + 8 * s + 2 * t;
        int kt = (col >> 1);
        float u0 = silu(c[s][0] + s_b1[col]);
        float u1 = silu(c[s][1] + s_b1[col + 1]);
        float u2 = silu(c[s][2] + s_b1[col]);
        float u3 = silu(c[s][3] + s_b1[col + 1]);
        splitbf(make_float2(u0, u1), thi[r0][kt], tlo[r0][kt]);
        splitbf(make_float2(u2, u3), thi[r1][kt], tlo[r1][kt]);
    }
    __syncthreads();

    // GEMM2: [64 x 128] @ [128 x 128]
    #pragma unroll
    for (int s = 0; s < 8; s++)
        #pragma unroll
        for (int q = 0; q < 4; q++) c[s][q] = 0.0f;
    {
        const uint4* bw = &g_nw2te[layer][0];
        #pragma unroll
        for (int ks = 0; ks < 8; ks++) {
            uint32_t a0h = thi[r0][8 * ks + t];
            uint32_t a1h = thi[r1][8 * ks + t];
            uint32_t a2h = thi[r0][8 * ks + 4 + t];
            uint32_t a3h = thi[r1][8 * ks + 4 + t];
            uint32_t a0l = tlo[r0][8 * ks + t];
            uint32_t a1l = tlo[r1][8 * ks + t];
            uint32_t a2l = tlo[r0][8 * ks + 4 + t];
            uint32_t a3l = tlo[r1][8 * ks + 4 + t];
            #pragma unroll
            for (int s = 0; s < 8; s++) {
                uint4 B = __ldg(bw + ((ks * 16 + sbase + s) * 32 + lane));
                MMA_BF16(c[s], a0h, a1h, a2h, a3h, B.x, B.z);
                MMA_BF16(c[s], a0l, a1l, a2l, a3l, B.x, B.z);
                MMA_BF16(c[s], a0h, a1h, a2h, a3h, B.y, B.w);
            }
        }
    }
    __syncthreads();   // all t reads done; ys overlays sbuf0

    // epilogue: y = D + b2 + h (residual), write transposed for LN
    {
        int nd0 = nb0 + r0; if (nd0 >= NNODE) nd0 = 0;
        int nd1 = nb0 + r1; if (nd1 >= NNODE) nd1 = 0;
        const float* hp0 = g_h + (size_t)nd0 * HD;
        const float* hp1 = g_h + (size_t)nd1 * HD;
        #pragma unroll
        for (int s = 0; s < 8; s++) {
            int col = n0 + 8 * s + 2 * t;
            float2 h0 = __ldg((const float2*)(hp0 + col));
            float2 h1 = __ldg((const float2*)(hp1 + col));
            ys[r0][col]     = c[s][0] + s_b2[col]     + h0.x;
            ys[r0][col + 1] = c[s][1] + s_b2[col + 1] + h0.y;
            ys[r1][col]     = c[s][2] + s_b2[col]     + h1.x;
            ys[r1][col + 1] = c[s][3] + s_b2[col + 1] + h1.y;
        }
    }
    __syncthreads();

    // LayerNorm: each warp handles 8 nodes
    float* hout = use_out ? out : g_h;
    #pragma unroll
    for (int tt = 0; tt < 8; tt++) {
        int e = warp * 8 + tt;
        int node = nb0 + e;
        float v0 = ys[e][lane +  0];
        float v1 = ys[e][lane + 32];
        float v2 = ys[e][lane + 64];
        float v3 = ys[e][lane + 96];
        float s  = v0 + v1 + v2 + v3;
        float ss = fmaf(v0, v0, fmaf(v1, v1, fmaf(v2, v2, v3 * v3)));
        #pragma unroll
        for (int o = 16; o; o >>= 1) {
            s  += __shfl_xor_sync(0xffffffffu, s, o);
            ss += __shfl_xor_sync(0xffffffffu, ss, o);
        }
        float mu  = s * (1.0f / 128.0f);
        float inv = rsqrtf(ss * (1.0f / 128.0f) - mu * mu + 1e-5f);
        if (node < NNODE) {
            float* dst = hout + (size_t)node * HD;
            dst[lane +  0] = fmaf(s_g[lane +  0], (v0 - mu) * inv, s_bb[lane +  0]);
            dst[lane + 32] = fmaf(s_g[lane + 32], (v1 - mu) * inv, s_bb[lane + 32]);
            dst[lane + 64] = fmaf(s_g[lane + 64], (v2 - mu) * inv, s_bb[lane + 64]);
            dst[lane + 96] = fmaf(s_g[lane + 96], (v3 - mu) * inv, s_bb[lane + 96]);
        }
    }
}

extern "C" void kernel_launch(void* const* d_in, const int* in_sizes, int n_in,
                              void* d_out, int out_size) {
    const int*   z   = (const int*)d_in[0];
    const float* pos = (const float*)d_in[1];
    const int*   ei  = (const int*)d_in[2];
    const float* emb = (const float*)d_in[3];
    const float* ew1 = (const float*)d_in[4];
    const float* eb1 = (const float*)d_in[5];
    const float* ew2 = (const float*)d_in[6];
    const float* eb2 = (const float*)d_in[7];
    const float* nw1 = (const float*)d_in[8];
    const float* nb1 = (const float*)d_in[9];
    const float* nw2 = (const float*)d_in[10];
    const float* nb2 = (const float*)d_in[11];
    const float* lng = (const float*)d_in[12];
    const float* lnb = (const float*)d_in[13];
    float* out = (float*)d_out;

    k_init<<<(NNODE * HD + 255) / 256, 256>>>(z, emb);
    k_d2<<<(NEDGE + 255) / 256, 256>>>(pos, ei);
    k_prepw<<<(NLAYER * 4096 + 255) / 256, 256>>>(ew2, 8, HD * HD, 0);
    k_prepw<<<(NLAYER * 8192 + 255) / 256, 256>>>(nw1, 16, 2 * HD * HD, 1);
    k_prepw<<<(NLAYER * 4096 + 255) / 256, 256>>>(nw2, 8, HD * HD, 2);

    const int pqgrid = (NNODE + TN - 1) / TN;   // 1563
    const int egrid  = NEDGE / TE;              // 12500
    const int ngrid  = (NNODE + TE - 1) / TE;   // 782

    for (int l = 0; l < NLAYER; l++) {
        const float* W1l = ew1 + (size_t)l * 257 * HD;
        k_pq<<<pqgrid, 256>>>(W1l);
        k_edge<<<egrid, 256>>>(ei, W1l, eb1 + l * HD, eb2 + l * HD, l);
        k_node<<<ngrid, 256>>>(nb1 + l * HD, nb2 + l * HD,
                               lng + l * HD, lnb + l * HD,
                               out, (l == NLAYER - 1) ? 1 : 0, l);
    }
}

// round 14
// speedup vs baseline: 1.8121x; 1.0408x over previous
#include <cuda_runtime.h>
#include <cuda_bf16.h>
#include <cstdint>

#define NNODE 50000
#define NEDGE 800000
#define HD 128
#define NLAYER 4
#define TE 64           // edges/nodes per block tile

__device__ float g_h[NNODE * HD];
__device__ float g_agg[NNODE * HD];
__device__ float g_P[NNODE * HD];
__device__ float g_Q[NNODE * HD];
__device__ float g_d2[NEDGE];
// fragment-major split-bf16 weight images:
// entry r=(ks*S+s)*32+lane -> uint4(B0hi,B0lo,B1hi,B1lo), col n=8s+(lane>>2),
// kpairs kp0=8ks+(lane&3), kp1=kp0+4 (S = N/8 s-values per ks).
__device__ uint4 g_w2te[NLAYER][4096];    // edge W2,  K=128, N=128
__device__ uint4 g_nw1te[NLAYER][8192];   // node W1,  K=256, N=128
__device__ uint4 g_nw2te[NLAYER][4096];   // node W2,  K=128, N=128
__device__ uint4 g_w1te[NLAYER][8192];    // edge W1 P||Q, K=128, N=256

__device__ __forceinline__ float silu(float x) {
    return x / (1.0f + __expf(-x));
}
__device__ __forceinline__ uint32_t packbf(float lo_e, float hi_e) {
    return ((uint32_t)__bfloat16_as_ushort(__float2bfloat16_rn(hi_e)) << 16)
         |  (uint32_t)__bfloat16_as_ushort(__float2bfloat16_rn(lo_e));
}
__device__ __forceinline__ void splitbf(float2 v, uint32_t& hiw, uint32_t& low) {
    __nv_bfloat16 h0 = __float2bfloat16_rn(v.x);
    __nv_bfloat16 h1 = __float2bfloat16_rn(v.y);
    hiw = ((uint32_t)__bfloat16_as_ushort(h1) << 16)
        |  (uint32_t)__bfloat16_as_ushort(h0);
    low = packbf(v.x - __bfloat162float(h0), v.y - __bfloat162float(h1));
}

// m16n8k16 bf16 mma, fp32 accumulate (sm_80+ PTX)
#define MMA_BF16(c, a0, a1, a2, a3, b0, b1) \
    asm volatile("mma.sync.aligned.m16n8k16.row.col.f32.bf16.bf16.f32 " \
        "{%0,%1,%2,%3}, {%4,%5,%6,%7}, {%8,%9}, {%0,%1,%2,%3};" \
        : "+f"((c)[0]), "+f"((c)[1]), "+f"((c)[2]), "+f"((c)[3]) \
        : "r"(a0), "r"(a1), "r"(a2), "r"(a3), "r"(b0), "r"(b1))

__global__ void k_init(const int* __restrict__ z, const float* __restrict__ emb) {
    int i = blockIdx.x * 256 + threadIdx.x;
    if (i < NNODE * HD) {
        g_h[i] = emb[(z[i >> 7] << 7) | (i & 127)];
        g_agg[i] = 0.0f;
    }
}

__global__ void k_d2(const float* __restrict__ pos, const int* __restrict__ ei) {
    int e = blockIdx.x * 256 + threadIdx.x;
    if (e < NEDGE) {
        int r = ei[e], c = ei[NEDGE + e];
        float dx = pos[3 * r + 0] - pos[3 * c + 0];
        float dy = pos[3 * r + 1] - pos[3 * c + 1];
        float dz = pos[3 * r + 2] - pos[3 * c + 2];
        g_d2[e] = dx * dx + dy * dy + dz * dz;
    }
}

// Fragment-major split-bf16 weight image builder (N=128 images).
// which: 0 -> g_w2te(K=128), 1 -> g_nw1te(K=256), 2 -> g_nw2te(K=128)
__global__ void k_prepw(const float* __restrict__ src, int ksteps,
                        int layer_stride, int which) {
    int per = ksteps * 512;
    int idx = blockIdx.x * 256 + threadIdx.x;
    if (idx >= NLAYER * per) return;
    int l = idx / per, r = idx % per;
    int ks = r >> 9, s = (r >> 5) & 15, lane = r & 31;
    int g = lane >> 2, t = lane & 3;
    int n = 8 * s + g;
    int kp0 = 8 * ks + t, kp1 = kp0 + 4;
    const float* W = src + (size_t)l * layer_stride;

    uint4 v;
    splitbf(make_float2(W[(size_t)(2 * kp0) * HD + n],
                        W[(size_t)(2 * kp0 + 1) * HD + n]), v.x, v.y);
    splitbf(make_float2(W[(size_t)(2 * kp1) * HD + n],
                        W[(size_t)(2 * kp1 + 1) * HD + n]), v.z, v.w);
    if (which == 0)      g_w2te[l][r] = v;
    else if (which == 1) g_nw1te[l][r] = v;
    else                 g_nw2te[l][r] = v;
}

// Fragment-major image for edge W1 as fused P||Q GEMM:
// B[k][n] = W1[k][n]           for n < 128   (P half)
//         = W1[128 + k][n-128] for n >= 128  (Q half)
// K=128 (ks 0..7), N=256 (s 0..31). ew1 layer stride = 257*128.
__global__ void k_prepw1(const float* __restrict__ ew1) {
    int idx = blockIdx.x * 256 + threadIdx.x;     // NLAYER * 8192
    if (idx >= NLAYER * 8192) return;
    int l = idx >> 13, r = idx & 8191;
    int ks = r >> 10, s = (r >> 5) & 31, lane = r & 31;
    int g = lane >> 2, t = lane & 3;
    int n = 8 * s + g;                 // 0..255
    int j = n & 127;                   // output col within W1
    int koff = (n >= 128) ? 128 : 0;   // P vs Q row block
    int kp0 = 8 * ks + t, kp1 = kp0 + 4;
    const float* W = ew1 + (size_t)l * 257 * HD;

    uint4 v;
    splitbf(make_float2(W[(size_t)(2 * kp0 + koff) * HD + j],
                        W[(size_t)(2 * kp0 + 1 + koff) * HD + j]), v.x, v.y);
    splitbf(make_float2(W[(size_t)(2 * kp1 + koff) * HD + j],
                        W[(size_t)(2 * kp1 + 1 + koff) * HD + j]), v.z, v.w);
    g_w1te[l][r] = v;
}

// P||Q = h @ [W1_top || W1_bot] on tensor cores.
// 64 nodes x 256 cols per block, 512 threads (16 warps):
// warp tile 16 nodes (warp&3) x 64 cols (warp>>2).
__global__ __launch_bounds__(512) void k_pq(int layer) {
    __shared__ uint32_t xhi[TE][68];
    __shared__ uint32_t xlo[TE][68];

    const int tid = threadIdx.x;
    const int warp = tid >> 5, lane = tid & 31;
    const int nb0 = blockIdx.x * TE;

    // gather h -> split-bf16 planes (16 warps, 4 rows each)
    for (int r = warp; r < TE; r += 16) {
        int node = nb0 + r;
        if (node >= NNODE) node = 0;
        const float* hp = g_h + (size_t)node * HD;
        #pragma unroll
        for (int s = 0; s < 2; s++) {
            int kp = lane + 32 * s;
            float2 hv = __ldg((const float2*)(hp + 2 * kp));
            splitbf(hv, xhi[r][kp], xlo[r][kp]);
        }
    }
    __syncthreads();

    const int g = lane >> 2, t = lane & 3;
    const int m0 = 16 * (warp & 3);
    const int sbase = (warp >> 2) * 8;   // global s base: 0,8,16,24
    const int n0 = 8 * sbase;            // col base: 0,64,128,192
    const int r0 = m0 + g, r1 = m0 + 8 + g;

    float c[8][4];
    #pragma unroll
    for (int s = 0; s < 8; s++)
        #pragma unroll
        for (int q = 0; q < 4; q++) c[s][q] = 0.0f;

    const uint4* bw = &g_w1te[layer][0];

    #pragma unroll
    for (int ks = 0; ks < 8; ks++) {
        uint32_t a0h = xhi[r0][8 * ks + t];
        uint32_t a1h = xhi[r1][8 * ks + t];
        uint32_t a2h = xhi[r0][8 * ks + 4 + t];
        uint32_t a3h = xhi[r1][8 * ks + 4 + t];
        uint32_t a0l = xlo[r0][8 * ks + t];
        uint32_t a1l = xlo[r1][8 * ks + t];
        uint32_t a2l = xlo[r0][8 * ks + 4 + t];
        uint32_t a3l = xlo[r1][8 * ks + 4 + t];
        #pragma unroll
        for (int s = 0; s < 8; s++) {
            uint4 B = __ldg(bw + ((ks * 32 + sbase + s) * 32 + lane));
            MMA_BF16(c[s], a0h, a1h, a2h, a3h, B.x, B.z);
            MMA_BF16(c[s], a0l, a1l, a2l, a3l, B.x, B.z);
            MMA_BF16(c[s], a0h, a1h, a2h, a3h, B.y, B.w);
        }
    }

    // epilogue: write fp32 P (cols 0..127) / Q (cols 128..255)
    {
        int nd0 = nb0 + r0, nd1 = nb0 + r1;
        #pragma unroll
        for (int s = 0; s < 8; s++) {
            int col = n0 + 8 * s + 2 * t;
            float* base = (col < 128) ? g_P : g_Q;
            int cc = col & 127;
            if (nd0 < NNODE)
                *(float2*)(base + (size_t)nd0 * HD + cc) = make_float2(c[s][0], c[s][1]);
            if (nd1 < NNODE)
                *(float2*)(base + (size_t)nd1 * HD + cc) = make_float2(c[s][2], c[s][3]);
        }
    }
}

// Edge kernel (Round-12, proven): tensor-core GEMM2 with coalesced B image.
__global__ __launch_bounds__(256) void k_edge(
    const int* __restrict__ ei,
    const float* __restrict__ W1,            // row 256 = d2 weights
    const float* __restrict__ b1,
    const float* __restrict__ b2, int layer)
{
    __shared__ uint32_t xhi[TE][68];
    __shared__ uint32_t xlo[TE][68];
    __shared__ int srow[TE], scols[TE];
    __shared__ float sd2[TE], s_b1[HD], s_wl[HD];

    const int tid = threadIdx.x;
    const int warp = tid >> 5, lane = tid & 31;
    const int e0 = blockIdx.x * TE;

    if (tid < TE) { srow[tid] = ei[e0 + tid]; sd2[tid] = g_d2[e0 + tid]; }
    else if (tid < 2 * TE) scols[tid - TE] = ei[NEDGE + e0 + (tid - TE)];
    if (tid < HD) {
        s_b1[tid] = __ldg(b1 + tid);
        s_wl[tid] = __ldg(W1 + 256 * HD + tid);
    }
    __syncthreads();

    for (int e = warp; e < TE; e += 8) {
        const float* pp = g_P + (size_t)srow[e] * HD;
        const float* qq = g_Q + (size_t)scols[e] * HD;
        float d2e = sd2[e];
        #pragma unroll
        for (int s = 0; s < 2; s++) {
            int kp = lane + 32 * s;
            float2 pv = __ldg((const float2*)(pp + 2 * kp));
            float2 qv = __ldg((const float2*)(qq + 2 * kp));
            float u0 = silu(pv.x + qv.x + d2e * s_wl[2 * kp]     + s_b1[2 * kp]);
            float u1 = silu(pv.y + qv.y + d2e * s_wl[2 * kp + 1] + s_b1[2 * kp + 1]);
            splitbf(make_float2(u0, u1), xhi[e][kp], xlo[e][kp]);
        }
    }
    __syncthreads();

    const int g = lane >> 2, t = lane & 3;
    const int m0 = 16 * (warp & 3);
    const int sbase = (warp >> 2) * 8;
    const int n0 = 8 * sbase;

    float c[8][4];
    #pragma unroll
    for (int s = 0; s < 8; s++)
        #pragma unroll
        for (int q = 0; q < 4; q++) c[s][q] = 0.0f;

    const uint4* bw = &g_w2te[layer][0];

    #pragma unroll
    for (int ks = 0; ks < 8; ks++) {
        uint32_t a0h = xhi[m0 + g][8 * ks + t];
        uint32_t a1h = xhi[m0 + 8 + g][8 * ks + t];
        uint32_t a2h = xhi[m0 + g][8 * ks + 4 + t];
        uint32_t a3h = xhi[m0 + 8 + g][8 * ks + 4 + t];
        uint32_t a0l = xlo[m0 + g][8 * ks + t];
        uint32_t a1l = xlo[m0 + 8 + g][8 * ks + t];
        uint32_t a2l = xlo[m0 + g][8 * ks + 4 + t];
        uint32_t a3l = xlo[m0 + 8 + g][8 * ks + 4 + t];
        #pragma unroll
        for (int s = 0; s < 8; s++) {
            uint4 B = __ldg(bw + ((ks * 16 + sbase + s) * 32 + lane));
            MMA_BF16(c[s], a0h, a1h, a2h, a3h, B.x, B.z);
            MMA_BF16(c[s], a0l, a1l, a2l, a3l, B.x, B.z);
            MMA_BF16(c[s], a0h, a1h, a2h, a3h, B.y, B.w);
        }
    }

    {
        float* ra = g_agg + (size_t)srow[m0 + g] * HD;
        float* rb = g_agg + (size_t)srow[m0 + 8 + g] * HD;
        #pragma unroll
        for (int s = 0; s < 8; s++) {
            int col = n0 + 8 * s + 2 * t;
            float bb0 = __ldg(b2 + col), bb1 = __ldg(b2 + col + 1);
            atomicAdd(ra + col,     silu(c[s][0] + bb0));
            atomicAdd(ra + col + 1, silu(c[s][1] + bb1));
            atomicAdd(rb + col,     silu(c[s][2] + bb0));
            atomicAdd(rb + col + 1, silu(c[s][3] + bb1));
        }
    }
}

// Node MLP + residual + LayerNorm on tensor cores (Round-13, proven).
__global__ __launch_bounds__(256) void k_node(
    const float* __restrict__ b1, const float* __restrict__ b2,
    const float* __restrict__ lng, const float* __restrict__ lnb,
    float* __restrict__ out, int use_out, int layer)
{
    __shared__ __align__(16) unsigned char sbuf0[64 * 132 * 4];
    __shared__ __align__(16) unsigned char sbuf1[64 * 132 * 4];
    __shared__ float s_b1[HD], s_b2[HD], s_g[HD], s_bb[HD];

    uint32_t (*xhi)[132] = (uint32_t(*)[132])sbuf0;
    uint32_t (*xlo)[132] = (uint32_t(*)[132])sbuf1;
    uint32_t (*thi)[68]  = (uint32_t(*)[68])sbuf0;
    uint32_t (*tlo)[68]  = (uint32_t(*)[68])sbuf1;
    float (*ys)[132]     = (float(*)[132])sbuf0;

    const int tid = threadIdx.x;
    const int warp = tid >> 5, lane = tid & 31;
    const int nb0 = blockIdx.x * TE;

    if (tid < HD) {
        s_b1[tid] = __ldg(b1 + tid);
        s_b2[tid] = __ldg(b2 + tid);
        s_g[tid]  = __ldg(lng + tid);
        s_bb[tid] = __ldg(lnb + tid);
    }

    for (int r = warp; r < TE; r += 8) {
        int node = nb0 + r;
        int valid = node < NNODE;
        if (!valid) node = 0;
        const float* hp = g_h + (size_t)node * HD;
        float* ap = g_agg + (size_t)node * HD;
        #pragma unroll
        for (int s = 0; s < 2; s++) {
            int kp = lane + 32 * s;
            float2 hv = __ldg((const float2*)(hp + 2 * kp));
            splitbf(hv, xhi[r][kp], xlo[r][kp]);
            float2 av = *(const float2*)(ap + 2 * kp);
            splitbf(av, xhi[r][64 + kp], xlo[r][64 + kp]);
            if (valid) *(float2*)(ap + 2 * kp) = make_float2(0.f, 0.f);
        }
    }
    __syncthreads();

    const int g = lane >> 2, t = lane & 3;
    const int m0 = 16 * (warp & 3);
    const int sbase = (warp >> 2) * 8;
    const int n0 = 8 * sbase;
    const int r0 = m0 + g, r1 = m0 + 8 + g;

    float c[8][4];
    #pragma unroll
    for (int s = 0; s < 8; s++)
        #pragma unroll
        for (int q = 0; q < 4; q++) c[s][q] = 0.0f;

    {
        const uint4* bw = &g_nw1te[layer][0];
        #pragma unroll
        for (int ks = 0; ks < 16; ks++) {
            uint32_t a0h = xhi[r0][8 * ks + t];
            uint32_t a1h = xhi[r1][8 * ks + t];
            uint32_t a2h = xhi[r0][8 * ks + 4 + t];
            uint32_t a3h = xhi[r1][8 * ks + 4 + t];
            uint32_t a0l = xlo[r0][8 * ks + t];
            uint32_t a1l = xlo[r1][8 * ks + t];
            uint32_t a2l = xlo[r0][8 * ks + 4 + t];
            uint32_t a3l = xlo[r1][8 * ks + 4 + t];
            #pragma unroll
            for (int s = 0; s < 8; s++) {
                uint4 B = __ldg(bw + ((ks * 16 + sbase + s) * 32 + lane));
                MMA_BF16(c[s], a0h, a1h, a2h, a3h, B.x, B.z);
                MMA_BF16(c[s], a0l, a1l, a2l, a3l, B.x, B.z);
                MMA_BF16(c[s], a0h, a1h, a2h, a3h, B.y, B.w);
            }
        }
    }
    __syncthreads();

    #pragma unroll
    for (int s = 0; s < 8; s++) {
        int col = n0 + 8 * s + 2 * t;
        int kt = (col >> 1);
        float u0 = silu(c[s][0] + s_b1[col]);
        float u1 = silu(c[s][1] + s_b1[col + 1]);
        float u2 = silu(c[s][2] + s_b1[col]);
        float u3 = silu(c[s][3] + s_b1[col + 1]);
        splitbf(make_float2(u0, u1), thi[r0][kt], tlo[r0][kt]);
        splitbf(make_float2(u2, u3), thi[r1][kt], tlo[r1][kt]);
    }
    __syncthreads();

    #pragma unroll
    for (int s = 0; s < 8; s++)
        #pragma unroll
        for (int q = 0; q < 4; q++) c[s][q] = 0.0f;
    {
        const uint4* bw = &g_nw2te[layer][0];
        #pragma unroll
        for (int ks = 0; ks < 8; ks++) {
            uint32_t a0h = thi[r0][8 * ks + t];
            uint32_t a1h = thi[r1][8 * ks + t];
            uint32_t a2h = thi[r0][8 * ks + 4 + t];
            uint32_t a3h = thi[r1][8 * ks + 4 + t];
            uint32_t a0l = tlo[r0][8 * ks + t];
            uint32_t a1l = tlo[r1][8 * ks + t];
            uint32_t a2l = tlo[r0][8 * ks + 4 + t];
            uint32_t a3l = tlo[r1][8 * ks + 4 + t];
            #pragma unroll
            for (int s = 0; s < 8; s++) {
                uint4 B = __ldg(bw + ((ks * 16 + sbase + s) * 32 + lane));
                MMA_BF16(c[s], a0h, a1h, a2h, a3h, B.x, B.z);
                MMA_BF16(c[s], a0l, a1l, a2l, a3l, B.x, B.z);
                MMA_BF16(c[s], a0h, a1h, a2h, a3h, B.y, B.w);
            }
        }
    }
    __syncthreads();

    {
        int nd0 = nb0 + r0; if (nd0 >= NNODE) nd0 = 0;
        int nd1 = nb0 + r1; if (nd1 >= NNODE) nd1 = 0;
        const float* hp0 = g_h + (size_t)nd0 * HD;
        const float* hp1 = g_h + (size_t)nd1 * HD;
        #pragma unroll
        for (int s = 0; s < 8; s++) {
            int col = n0 + 8 * s + 2 * t;
            float2 h0 = __ldg((const float2*)(hp0 + col));
            float2 h1 = __ldg((const float2*)(hp1 + col));
            ys[r0][col]     = c[s][0] + s_b2[col]     + h0.x;
            ys[r0][col + 1] = c[s][1] + s_b2[col + 1] + h0.y;
            ys[r1][col]     = c[s][2] + s_b2[col]     + h1.x;
            ys[r1][col + 1] = c[s][3] + s_b2[col + 1] + h1.y;
        }
    }
    __syncthreads();

    float* hout = use_out ? out : g_h;
    #pragma unroll
    for (int tt = 0; tt < 8; tt++) {
        int e = warp * 8 + tt;
        int node = nb0 + e;
        float v0 = ys[e][lane +  0];
        float v1 = ys[e][lane + 32];
        float v2 = ys[e][lane + 64];
        float v3 = ys[e][lane + 96];
        float s  = v0 + v1 + v2 + v3;
        float ss = fmaf(v0, v0, fmaf(v1, v1, fmaf(v2, v2, v3 * v3)));
        #pragma unroll
        for (int o = 16; o; o >>= 1) {
            s  += __shfl_xor_sync(0xffffffffu, s, o);
            ss += __shfl_xor_sync(0xffffffffu, ss, o);
        }
        float mu  = s * (1.0f / 128.0f);
        float inv = rsqrtf(ss * (1.0f / 128.0f) - mu * mu + 1e-5f);
        if (node < NNODE) {
            float* dst = hout + (size_t)node * HD;
            dst[lane +  0] = fmaf(s_g[lane +  0], (v0 - mu) * inv, s_bb[lane +  0]);
            dst[lane + 32] = fmaf(s_g[lane + 32], (v1 - mu) * inv, s_bb[lane + 32]);
            dst[lane + 64] = fmaf(s_g[lane + 64], (v2 - mu) * inv, s_bb[lane + 64]);
            dst[lane + 96] = fmaf(s_g[lane + 96], (v3 - mu) * inv, s_bb[lane + 96]);
        }
    }
}

extern "C" void kernel_launch(void* const* d_in, const int* in_sizes, int n_in,
                              void* d_out, int out_size) {
    const int*   z   = (const int*)d_in[0];
    const float* pos = (const float*)d_in[1];
    const int*   ei  = (const int*)d_in[2];
    const float* emb = (const float*)d_in[3];
    const float* ew1 = (const float*)d_in[4];
    const float* eb1 = (const float*)d_in[5];
    const float* ew2 = (const float*)d_in[6];
    const float* eb2 = (const float*)d_in[7];
    const float* nw1 = (const float*)d_in[8];
    const float* nb1 = (const float*)d_in[9];
    const float* nw2 = (const float*)d_in[10];
    const float* nb2 = (const float*)d_in[11];
    const float* lng = (const float*)d_in[12];
    const float* lnb = (const float*)d_in[13];
    float* out = (float*)d_out;

    k_init<<<(NNODE * HD + 255) / 256, 256>>>(z, emb);
    k_d2<<<(NEDGE + 255) / 256, 256>>>(pos, ei);
    k_prepw<<<(NLAYER * 4096 + 255) / 256, 256>>>(ew2, 8, HD * HD, 0);
    k_prepw<<<(NLAYER * 8192 + 255) / 256, 256>>>(nw1, 16, 2 * HD * HD, 1);
    k_prepw<<<(NLAYER * 4096 + 255) / 256, 256>>>(nw2, 8, HD * HD, 2);
    k_prepw1<<<(NLAYER * 8192 + 255) / 256, 256>>>(ew1);

    const int pqgrid = (NNODE + TE - 1) / TE;   // 782
    const int egrid  = NEDGE / TE;              // 12500
    const int ngrid  = (NNODE + TE - 1) / TE;   // 782

    for (int l = 0; l < NLAYER; l++) {
        const float* W1l = ew1 + (size_t)l * 257 * HD;
        k_pq<<<pqgrid, 512>>>(l);
        k_edge<<<egrid, 256>>>(ei, W1l, eb1 + l * HD, eb2 + l * HD, l);
        k_node<<<ngrid, 256>>>(nb1 + l * HD, nb2 + l * HD,
                               lng + l * HD, lnb + l * HD,
                               out, (l == NLAYER - 1) ? 1 : 0, l);
    }
}